// round 4
// baseline (speedup 1.0000x reference)
#include <cuda_runtime.h>
#include <cstdint>

// Problem constants
#define B_  8
#define N_  2048
#define FIN 256
#define FOUT 64

// Scratch (device globals: allocation-free)
__device__ float g_Wh[B_ * N_ * FOUT];   // 4 MB
__device__ float g_Wh1[B_ * N_];
__device__ float g_Wh2[B_ * N_];
__device__ float g_maxWh2[B_];

// ---------------------------------------------------------------------------
// K0: Wh = h @ W.   Grid: (B*N/64) blocks of 256 threads, 64 rows per block.
// ---------------------------------------------------------------------------
__global__ void k_gemm1(const float* __restrict__ h, const float* __restrict__ W) {
    __shared__ __align__(16) float hs[64][64];    // h tile  [row][k]
    __shared__ __align__(16) float Wst[64][68];   // W tile transposed [col][k], padded

    int tid = threadIdx.x;
    int tx = tid & 63, ty = tid >> 6;
    int r0 = blockIdx.x * 64;

    float acc[16];
#pragma unroll
    for (int i = 0; i < 16; i++) acc[i] = 0.f;

    for (int kt = 0; kt < 4; kt++) {
        __syncthreads();
#pragma unroll
        for (int l = 0; l < 16; l++) {
            int idx = l * 256 + tid;
            int r = idx >> 6, kk = idx & 63;
            hs[r][kk] = h[(size_t)(r0 + r) * FIN + kt * 64 + kk];
        }
#pragma unroll
        for (int l = 0; l < 16; l++) {
            int idx = l * 256 + tid;
            int kk = idx >> 6, c = idx & 63;
            Wst[c][kk] = W[(size_t)(kt * 64 + kk) * FOUT + c];
        }
        __syncthreads();

        for (int kk = 0; kk < 64; kk += 4) {
            float4 wv = *(const float4*)&Wst[tx][kk];
#pragma unroll
            for (int i = 0; i < 16; i++) {
                float4 hv = *(const float4*)&hs[ty + 4 * i][kk];
                acc[i] += hv.x * wv.x;
                acc[i] += hv.y * wv.y;
                acc[i] += hv.z * wv.z;
                acc[i] += hv.w * wv.w;
            }
        }
    }
#pragma unroll
    for (int i = 0; i < 16; i++)
        g_Wh[(size_t)(r0 + ty + 4 * i) * FOUT + tx] = acc[i];
}

// ---------------------------------------------------------------------------
// K0b: Wh1[r] = Wh[r,:]·a[0:64],  Wh2[r] = Wh[r,:]·a[64:128]
// ---------------------------------------------------------------------------
__global__ void k_rowproj(const float* __restrict__ a) {
    int tid = threadIdx.x;
    int lane = tid & 31;
    int warp_g = blockIdx.x * 8 + (tid >> 5);

    float a0l = a[lane], a0h = a[lane + 32];
    float a1l = a[64 + lane], a1h = a[96 + lane];

    int row0 = warp_g * 32;
    for (int r = 0; r < 32; r++) {
        int row = row0 + r;
        float wl = g_Wh[(size_t)row * FOUT + lane];
        float wh = g_Wh[(size_t)row * FOUT + lane + 32];
        float s1 = wl * a0l + wh * a0h;
        float s2 = wl * a1l + wh * a1h;
#pragma unroll
        for (int d = 16; d > 0; d >>= 1) {
            s1 += __shfl_xor_sync(0xffffffffu, s1, d);
            s2 += __shfl_xor_sync(0xffffffffu, s2, d);
        }
        if (lane == 0) {
            g_Wh1[row] = s1;
            g_Wh2[row] = s2;
        }
    }
}

// ---------------------------------------------------------------------------
// K0c: per-batch max of Wh2.
// ---------------------------------------------------------------------------
__global__ void k_maxwh2() {
    __shared__ float red[256];
    int b = blockIdx.x;
    float m = -1e30f;
    for (int i = threadIdx.x; i < N_; i += 256)
        m = fmaxf(m, g_Wh2[(size_t)b * N_ + i]);
    red[threadIdx.x] = m;
    __syncthreads();
    for (int s = 128; s > 0; s >>= 1) {
        if (threadIdx.x < s) red[threadIdx.x] = fmaxf(red[threadIdx.x], red[threadIdx.x + s]);
        __syncthreads();
    }
    if (threadIdx.x == 0) g_maxWh2[b] = red[0];
}

// ---------------------------------------------------------------------------
// K1: fused masked-softmax attention + PV product + ELU.
// Grid: 256 blocks (8 batches x 32 i-tiles of 64 rows), 256 threads.
//
// Phase 2: 4x4 per-thread micro-tile, warp-mapped so Whs float4 reads depend
// only on cx (16 distinct/warp) and Ps float4 reads depend only on ry
// (2 distinct/warp -> broadcast). FMA via fma.rn.f32x2.
// ---------------------------------------------------------------------------
__global__ void __launch_bounds__(256, 4) k_attn(const int* __restrict__ adj,
                                                 float* __restrict__ out) {
    __shared__ __align__(16) float Whs[64][68];   // Wh j-tile [j][c], padded
    __shared__ __align__(16) float Ps[64][64];    // P tile   [row][j]
    __shared__ float wh1s[64], Mr[64], ls[64], Wh2s[64];

    int tid = threadIdx.x;
    int b  = blockIdx.x >> 5;
    int i0 = (blockIdx.x & 31) * 64;
    size_t rowbase = (size_t)b * N_ + i0;

    if (tid < 64) {
        float w1 = g_Wh1[rowbase + tid];
        wh1s[tid] = w1;
        float s = w1 + g_maxWh2[b];
        Mr[tid] = s > 0.f ? s : 0.2f * s;
        ls[tid] = 0.f;
    }

    // phase-1 mapping: column jx, row-group ry4 (16 rows each, stride 4)
    int jx = tid & 63, ry4 = tid >> 6;
    // phase-2 mapping: cols [4cx,4cx+4), rows {ry, ry+16, ry+32, ry+48}
    int cx = tid & 15, ry = tid >> 4;

    unsigned long long acc[4][2];
#pragma unroll
    for (int r = 0; r < 4; r++) { acc[r][0] = 0ull; acc[r][1] = 0ull; }

    float lp[16];
#pragma unroll
    for (int k = 0; k < 16; k++) lp[k] = 0.f;

    const int* adjbase = adj + rowbase * N_;

    for (int jt = 0; jt < N_; jt += 64) {
        __syncthreads();   // previous phase2 done before overwriting tiles
#pragma unroll
        for (int l = 0; l < 16; l++) {
            int idx = l * 256 + tid;
            int j = idx >> 6, c = idx & 63;
            Whs[j][c] = g_Wh[((size_t)b * N_ + jt + j) * FOUT + c];
        }
        if (tid < 64) Wh2s[tid] = g_Wh2[(size_t)b * N_ + jt + tid];
        __syncthreads();

        // ---- phase 1: attention probabilities ----
        {
            float wh2v = Wh2s[jx];
#pragma unroll
            for (int k = 0; k < 16; k++) {
                int row = ry4 + 4 * k;
                float s = wh1s[row] + wh2v;
                float e = s > 0.f ? s : 0.2f * s;
                int av = adjbase[(size_t)row * N_ + jt + jx];
                float p = (av > 0) ? __expf(e - Mr[row]) : 0.f;
                Ps[row][jx] = p;
                lp[k] += p;
            }
        }
        __syncthreads();

        // ---- phase 2: acc += P @ WhTile (f32x2 packed FMA) ----
        for (int kk = 0; kk < 64; kk += 4) {
            float4 pv[4];
#pragma unroll
            for (int r = 0; r < 4; r++)
                pv[r] = *(const float4*)&Ps[ry + 16 * r][kk];
#pragma unroll
            for (int s2 = 0; s2 < 4; s2++) {
                float4 wv = *(const float4*)&Whs[kk + s2][4 * cx];
                unsigned long long w0, w1;
                asm("mov.b64 %0, {%1, %2};" : "=l"(w0) : "f"(wv.x), "f"(wv.y));
                asm("mov.b64 %0, {%1, %2};" : "=l"(w1) : "f"(wv.z), "f"(wv.w));
#pragma unroll
                for (int r = 0; r < 4; r++) {
                    float p = (s2 == 0) ? pv[r].x :
                              (s2 == 1) ? pv[r].y :
                              (s2 == 2) ? pv[r].z : pv[r].w;
                    unsigned long long pp;
                    asm("mov.b64 %0, {%1, %1};" : "=l"(pp) : "f"(p));
                    asm("fma.rn.f32x2 %0, %1, %2, %0;" : "+l"(acc[r][0]) : "l"(pp), "l"(w0));
                    asm("fma.rn.f32x2 %0, %1, %2, %0;" : "+l"(acc[r][1]) : "l"(pp), "l"(w1));
                }
            }
        }
    }

    // ---- reduce lane-partial denominators into ls ----
#pragma unroll
    for (int k = 0; k < 16; k++) {
        float v = lp[k];
        v += __shfl_xor_sync(0xffffffffu, v, 16);
        v += __shfl_xor_sync(0xffffffffu, v, 8);
        v += __shfl_xor_sync(0xffffffffu, v, 4);
        v += __shfl_xor_sync(0xffffffffu, v, 2);
        v += __shfl_xor_sync(0xffffffffu, v, 1);
        if ((tid & 31) == 0) atomicAdd(&ls[ry4 + 4 * k], v);
    }
    __syncthreads();

    // ---- epilogue: normalize + ELU + store ----
#pragma unroll
    for (int r = 0; r < 4; r++) {
        int row = ry + 16 * r;
        float inv = 1.f / ls[row];
        float x0, x1, x2, x3;
        asm("mov.b64 {%0, %1}, %2;" : "=f"(x0), "=f"(x1) : "l"(acc[r][0]));
        asm("mov.b64 {%0, %1}, %2;" : "=f"(x2), "=f"(x3) : "l"(acc[r][1]));
        float4 o;
        float v;
        v = x0 * inv; o.x = v > 0.f ? v : expm1f(v);
        v = x1 * inv; o.y = v > 0.f ? v : expm1f(v);
        v = x2 * inv; o.z = v > 0.f ? v : expm1f(v);
        v = x3 * inv; o.w = v > 0.f ? v : expm1f(v);
        *(float4*)(out + (rowbase + row) * FOUT + 4 * cx) = o;
    }
}

// ---------------------------------------------------------------------------
extern "C" void kernel_launch(void* const* d_in, const int* in_sizes, int n_in,
                              void* d_out, int out_size) {
    const float* h   = (const float*)d_in[0];
    const int*   adj = (const int*)d_in[1];
    const float* W   = (const float*)d_in[2];
    const float* a   = (const float*)d_in[3];
    float* out = (float*)d_out;

    k_gemm1<<<(B_ * N_) / 64, 256>>>(h, W);
    k_rowproj<<<64, 256>>>(a);
    k_maxwh2<<<B_, 256>>>();
    k_attn<<<(B_ * N_) / 64, 256>>>(adj, out);
}

// round 5
// speedup vs baseline: 1.7141x; 1.7141x over previous
#include <cuda_runtime.h>
#include <cstdint>

// Problem constants
#define B_  8
#define N_  2048
#define FIN 256
#define FOUT 64
#define NSPLIT 4
#define JCHUNK (N_ / NSPLIT)   // 512

// Scratch (device globals: allocation-free)
__device__ float g_Wh[B_ * N_ * FOUT];                 // 4 MB
__device__ float g_Wh1[B_ * N_];
__device__ float g_Wh2[B_ * N_];
__device__ float g_maxWh2[B_];
__device__ float g_accp[NSPLIT * B_ * N_ * FOUT];      // 16 MB partial numerators
__device__ float g_lpart[NSPLIT * B_ * N_];            // partial denominators

// ---------------------------------------------------------------------------
// K0: Wh = h @ W, with fused epilogue computing Wh1 = Wh·a[0:64],
//     Wh2 = Wh·a[64:128] from the smem-resident tile.
// Grid: 256 blocks x 256 threads, 64 rows per block.
// ---------------------------------------------------------------------------
__global__ void k_gemm1(const float* __restrict__ h, const float* __restrict__ W,
                        const float* __restrict__ a) {
    __shared__ __align__(16) float hs[64][68];    // h tile [row][k] (reused for Wh tile)
    __shared__ __align__(16) float Wst[64][68];   // W tile transposed [col][k]
    __shared__ float as[128];

    int tid = threadIdx.x;
    int tx = tid & 63, ty = tid >> 6;
    int r0 = blockIdx.x * 64;

    if (tid < 128) as[tid] = a[tid];

    float acc[16];
#pragma unroll
    for (int i = 0; i < 16; i++) acc[i] = 0.f;

    for (int kt = 0; kt < 4; kt++) {
        __syncthreads();
#pragma unroll
        for (int l = 0; l < 16; l++) {
            int idx = l * 256 + tid;
            int r = idx >> 6, kk = idx & 63;
            hs[r][kk] = h[(size_t)(r0 + r) * FIN + kt * 64 + kk];
        }
#pragma unroll
        for (int l = 0; l < 16; l++) {
            int idx = l * 256 + tid;
            int kk = idx >> 6, c = idx & 63;
            Wst[c][kk] = W[(size_t)(kt * 64 + kk) * FOUT + c];
        }
        __syncthreads();

        for (int kk = 0; kk < 64; kk += 4) {
            float4 wv = *(const float4*)&Wst[tx][kk];
#pragma unroll
            for (int i = 0; i < 16; i++) {
                float4 hv = *(const float4*)&hs[ty + 4 * i][kk];
                acc[i] += hv.x * wv.x;
                acc[i] += hv.y * wv.y;
                acc[i] += hv.z * wv.z;
                acc[i] += hv.w * wv.w;
            }
        }
    }

    __syncthreads();   // done reading hs; reuse it for the Wh tile
#pragma unroll
    for (int i = 0; i < 16; i++) {
        int row = ty + 4 * i;
        g_Wh[(size_t)(r0 + row) * FOUT + tx] = acc[i];
        hs[row][tx] = acc[i];
    }
    __syncthreads();

    // Epilogue: row dots with a (4 threads per row, 16 cols each)
    {
        int row = tid >> 2, q = tid & 3;
        float s1 = 0.f, s2 = 0.f;
#pragma unroll
        for (int i = 0; i < 16; i++) {
            int c = q * 16 + i;
            float v = hs[row][c];
            s1 += v * as[c];
            s2 += v * as[64 + c];
        }
        s1 += __shfl_xor_sync(0xffffffffu, s1, 1);
        s1 += __shfl_xor_sync(0xffffffffu, s1, 2);
        s2 += __shfl_xor_sync(0xffffffffu, s2, 1);
        s2 += __shfl_xor_sync(0xffffffffu, s2, 2);
        if (q == 0) {
            g_Wh1[r0 + row] = s1;
            g_Wh2[r0 + row] = s2;
        }
    }
}

// ---------------------------------------------------------------------------
// K0c: per-batch max of Wh2.
// ---------------------------------------------------------------------------
__global__ void k_maxwh2() {
    __shared__ float red[256];
    int b = blockIdx.x;
    float m = -1e30f;
    for (int i = threadIdx.x; i < N_; i += 256)
        m = fmaxf(m, g_Wh2[(size_t)b * N_ + i]);
    red[threadIdx.x] = m;
    __syncthreads();
    for (int s = 128; s > 0; s >>= 1) {
        if (threadIdx.x < s) red[threadIdx.x] = fmaxf(red[threadIdx.x], red[threadIdx.x + s]);
        __syncthreads();
    }
    if (threadIdx.x == 0) g_maxWh2[b] = red[0];
}

// ---------------------------------------------------------------------------
// K1: fused masked-softmax attention + PV product, SPLIT over j (4-way).
// Grid: 1024 blocks (8 b x 32 i-tiles x 4 j-splits), 256 threads.
// Partial acc / l are additive because M_i is a fixed analytic bound.
// Phase 1: int4 adj loads, float4 Ps stores.
// Phase 2: 4x4 per-thread micro-tile, broadcast-friendly, fma.rn.f32x2.
// ---------------------------------------------------------------------------
__global__ void __launch_bounds__(256) k_attn(const int* __restrict__ adj) {
    __shared__ __align__(16) float Whs[64][68];   // Wh j-tile [j][c], padded
    __shared__ __align__(16) float Ps[64][64];    // P tile   [row][j]
    __shared__ float wh1s[64], Mr[64], ls[64];
    __shared__ __align__(16) float Wh2s[64];

    int tid = threadIdx.x;
    int split = blockIdx.x & (NSPLIT - 1);
    int tile  = blockIdx.x >> 2;
    int b  = tile >> 5;
    int i0 = (tile & 31) * 64;
    size_t rowbase = (size_t)b * N_ + i0;

    if (tid < 64) {
        float w1 = g_Wh1[rowbase + tid];
        wh1s[tid] = w1;
        float s = w1 + g_maxWh2[b];
        Mr[tid] = s > 0.f ? s : 0.2f * s;
        ls[tid] = 0.f;
    }

    // shared thread mapping for both phases:
    // cx = tid&15 -> j-group (phase1) / col-group (phase2)
    // ry = tid>>4 -> rows {ry, ry+16, ry+32, ry+48}
    int cx = tid & 15, ry = tid >> 4;
    int tjx = cx * 4;

    unsigned long long acc[4][2];
#pragma unroll
    for (int r = 0; r < 4; r++) { acc[r][0] = 0ull; acc[r][1] = 0ull; }
    float lp[4] = {0.f, 0.f, 0.f, 0.f};

    const int* adjbase = adj + rowbase * N_;
    int jt0 = split * JCHUNK;

    for (int jt = jt0; jt < jt0 + JCHUNK; jt += 64) {
        __syncthreads();   // previous phase2 done before overwriting tiles
#pragma unroll
        for (int l = 0; l < 16; l++) {
            int idx = l * 256 + tid;
            int j = idx >> 6, c = idx & 63;
            Whs[j][c] = g_Wh[((size_t)b * N_ + jt + j) * FOUT + c];
        }
        if (tid < 64) Wh2s[tid] = g_Wh2[(size_t)b * N_ + jt + tid];
        __syncthreads();

        // ---- phase 1: attention probabilities (vectorized x4 in j) ----
        {
            float4 w2v = *(const float4*)&Wh2s[tjx];
#pragma unroll
            for (int k = 0; k < 4; k++) {
                int row = ry + 16 * k;
                int4 av = *(const int4*)&adjbase[(size_t)row * N_ + jt + tjx];
                float w1v = wh1s[row], mrv = Mr[row];
                float4 p;
                float s;
                s = w1v + w2v.x; s = s > 0.f ? s : 0.2f * s;
                p.x = (av.x > 0) ? __expf(s - mrv) : 0.f;
                s = w1v + w2v.y; s = s > 0.f ? s : 0.2f * s;
                p.y = (av.y > 0) ? __expf(s - mrv) : 0.f;
                s = w1v + w2v.z; s = s > 0.f ? s : 0.2f * s;
                p.z = (av.z > 0) ? __expf(s - mrv) : 0.f;
                s = w1v + w2v.w; s = s > 0.f ? s : 0.2f * s;
                p.w = (av.w > 0) ? __expf(s - mrv) : 0.f;
                *(float4*)&Ps[row][tjx] = p;
                lp[k] += (p.x + p.y) + (p.z + p.w);
            }
        }
        __syncthreads();

        // ---- phase 2: acc += P @ WhTile (f32x2 packed FMA) ----
        for (int kk = 0; kk < 64; kk += 4) {
            float4 pv[4];
#pragma unroll
            for (int r = 0; r < 4; r++)
                pv[r] = *(const float4*)&Ps[ry + 16 * r][kk];
#pragma unroll
            for (int s2 = 0; s2 < 4; s2++) {
                float4 wv = *(const float4*)&Whs[kk + s2][4 * cx];
                unsigned long long w0, w1;
                asm("mov.b64 %0, {%1, %2};" : "=l"(w0) : "f"(wv.x), "f"(wv.y));
                asm("mov.b64 %0, {%1, %2};" : "=l"(w1) : "f"(wv.z), "f"(wv.w));
#pragma unroll
                for (int r = 0; r < 4; r++) {
                    float p = (s2 == 0) ? pv[r].x :
                              (s2 == 1) ? pv[r].y :
                              (s2 == 2) ? pv[r].z : pv[r].w;
                    unsigned long long pp;
                    asm("mov.b64 %0, {%1, %1};" : "=l"(pp) : "f"(p));
                    asm("fma.rn.f32x2 %0, %1, %2, %0;" : "+l"(acc[r][0]) : "l"(pp), "l"(w0));
                    asm("fma.rn.f32x2 %0, %1, %2, %0;" : "+l"(acc[r][1]) : "l"(pp), "l"(w1));
                }
            }
        }
    }

    // ---- reduce lane-partial denominators into ls (16-lane groups) ----
#pragma unroll
    for (int k = 0; k < 4; k++) {
        float v = lp[k];
        v += __shfl_xor_sync(0xffffffffu, v, 1);
        v += __shfl_xor_sync(0xffffffffu, v, 2);
        v += __shfl_xor_sync(0xffffffffu, v, 4);
        v += __shfl_xor_sync(0xffffffffu, v, 8);
        if ((tid & 15) == 0) atomicAdd(&ls[ry + 16 * k], v);
    }
    __syncthreads();

    // ---- store partials (no normalization here) ----
    size_t abase = (size_t)split * (B_ * N_) + rowbase;
    if (tid < 64) g_lpart[abase + tid] = ls[tid];
#pragma unroll
    for (int r = 0; r < 4; r++) {
        int row = ry + 16 * r;
        float x0, x1, x2, x3;
        asm("mov.b64 {%0, %1}, %2;" : "=f"(x0), "=f"(x1) : "l"(acc[r][0]));
        asm("mov.b64 {%0, %1}, %2;" : "=f"(x2), "=f"(x3) : "l"(acc[r][1]));
        float4 o = {x0, x1, x2, x3};
        *(float4*)&g_accp[(abase + row) * FOUT + 4 * cx] = o;
    }
}

// ---------------------------------------------------------------------------
// K2: combine split partials, normalize, ELU, store.
// Grid: 1024 blocks x 256 threads, one float4 per thread.
// ---------------------------------------------------------------------------
__global__ void k_final(float* __restrict__ out) {
    int t = blockIdx.x * 256 + threadIdx.x;
    int row = t >> 4;
    int c4 = (t & 15) * 4;

    float l = 0.f;
    float4 s = {0.f, 0.f, 0.f, 0.f};
#pragma unroll
    for (int sp = 0; sp < NSPLIT; sp++) {
        size_t base = (size_t)sp * (B_ * N_) + row;
        l += g_lpart[base];
        float4 v = *(const float4*)&g_accp[base * FOUT + c4];
        s.x += v.x; s.y += v.y; s.z += v.z; s.w += v.w;
    }
    float inv = 1.f / l;
    float v;
    float4 o;
    v = s.x * inv; o.x = v > 0.f ? v : expm1f(v);
    v = s.y * inv; o.y = v > 0.f ? v : expm1f(v);
    v = s.z * inv; o.z = v > 0.f ? v : expm1f(v);
    v = s.w * inv; o.w = v > 0.f ? v : expm1f(v);
    *(float4*)&out[(size_t)row * FOUT + c4] = o;
}

// ---------------------------------------------------------------------------
extern "C" void kernel_launch(void* const* d_in, const int* in_sizes, int n_in,
                              void* d_out, int out_size) {
    const float* h   = (const float*)d_in[0];
    const int*   adj = (const int*)d_in[1];
    const float* W   = (const float*)d_in[2];
    const float* a   = (const float*)d_in[3];
    float* out = (float*)d_out;

    k_gemm1<<<(B_ * N_) / 64, 256>>>(h, W, a);
    k_maxwh2<<<B_, 256>>>();
    k_attn<<<(B_ * N_ / 64) * NSPLIT, 256>>>(adj);
    k_final<<<(B_ * N_ * FOUT) / 1024, 256>>>(out);
}

// round 7
// speedup vs baseline: 1.9340x; 1.1283x over previous
#include <cuda_runtime.h>
#include <cuda_fp16.h>
#include <cstdint>

// Problem constants
#define B_  8
#define N_  2048
#define FIN 256
#define FOUT 64
#define NSPLIT 4
#define JCHUNK (N_ / NSPLIT)   // 512
#define NCHUNK (JCHUNK / 64)   // 8

// Scratch (device globals: allocation-free)
__device__ __half g_WhT[B_ * FOUT * N_];           // [b][c][j] fp16, 2 MB
__device__ float  g_Wh1[B_ * N_];
__device__ float  g_Wh2[B_ * N_];
__device__ float  g_maxWh2[B_];
__device__ float  g_accp[NSPLIT * B_ * N_ * FOUT]; // 16.8 MB partial numerators
__device__ float  g_lpart[NSPLIT * B_ * N_];       // partial denominators

__device__ __forceinline__ uint32_t smem_u32(const void* p) {
    uint32_t a;
    asm("{ .reg .u64 t; cvta.to.shared.u64 t, %1; cvt.u32.u64 %0, t; }" : "=r"(a) : "l"(p));
    return a;
}

// ---------------------------------------------------------------------------
// K0: Wh = h @ W; epilogue computes Wh1/Wh2 and writes transposed fp16 WhT.
// Grid: 256 blocks x 256 threads, 64 rows per block.
// ---------------------------------------------------------------------------
__global__ void k_gemm1(const float* __restrict__ h, const float* __restrict__ W,
                        const float* __restrict__ a) {
    __shared__ __align__(16) float hs[64][68];
    __shared__ __align__(16) float Wst[64][68];
    __shared__ float as[128];

    int tid = threadIdx.x;
    int tx = tid & 63, ty = tid >> 6;
    int r0 = blockIdx.x * 64;

    if (tid < 128) as[tid] = a[tid];

    float acc[16];
#pragma unroll
    for (int i = 0; i < 16; i++) acc[i] = 0.f;

    for (int kt = 0; kt < 4; kt++) {
        __syncthreads();
#pragma unroll
        for (int l = 0; l < 16; l++) {
            int idx = l * 256 + tid;
            int r = idx >> 6, kk = idx & 63;
            hs[r][kk] = h[(size_t)(r0 + r) * FIN + kt * 64 + kk];
        }
#pragma unroll
        for (int l = 0; l < 16; l++) {
            int idx = l * 256 + tid;
            int kk = idx >> 6, c = idx & 63;
            Wst[c][kk] = W[(size_t)(kt * 64 + kk) * FOUT + c];
        }
        __syncthreads();

        for (int kk = 0; kk < 64; kk += 4) {
            float4 wv = *(const float4*)&Wst[tx][kk];
#pragma unroll
            for (int i = 0; i < 16; i++) {
                float4 hv = *(const float4*)&hs[ty + 4 * i][kk];
                acc[i] += hv.x * wv.x;
                acc[i] += hv.y * wv.y;
                acc[i] += hv.z * wv.z;
                acc[i] += hv.w * wv.w;
            }
        }
    }

    __syncthreads();
#pragma unroll
    for (int i = 0; i < 16; i++) hs[ty + 4 * i][tx] = acc[i];
    __syncthreads();

    int b  = r0 >> 11;        // batch
    int j0 = r0 & 2047;       // j offset within batch

    // Wh1/Wh2: 4 threads per row
    {
        int row = tid >> 2, q = tid & 3;
        float s1 = 0.f, s2 = 0.f;
#pragma unroll
        for (int i = 0; i < 16; i++) {
            int c = q * 16 + i;
            float v = hs[row][c];
            s1 += v * as[c];
            s2 += v * as[64 + c];
        }
        s1 += __shfl_xor_sync(0xffffffffu, s1, 1);
        s1 += __shfl_xor_sync(0xffffffffu, s1, 2);
        s2 += __shfl_xor_sync(0xffffffffu, s2, 1);
        s2 += __shfl_xor_sync(0xffffffffu, s2, 2);
        if (q == 0) {
            g_Wh1[r0 + row] = s1;
            g_Wh2[r0 + row] = s2;
        }
    }

    // WhT[b][c][j0..j0+63] fp16 (transpose from hs)
    {
        int c = tid >> 2, q = tid & 3;   // 64 cols x 4 j-quarters
        __half2 hh[8];
#pragma unroll
        for (int i = 0; i < 8; i++)
            hh[i] = __floats2half2_rn(hs[q * 16 + 2 * i][c], hs[q * 16 + 2 * i + 1][c]);
        uint4 u0 = make_uint4(*(uint32_t*)&hh[0], *(uint32_t*)&hh[1],
                              *(uint32_t*)&hh[2], *(uint32_t*)&hh[3]);
        uint4 u1 = make_uint4(*(uint32_t*)&hh[4], *(uint32_t*)&hh[5],
                              *(uint32_t*)&hh[6], *(uint32_t*)&hh[7]);
        __half* dst = g_WhT + ((size_t)(b * FOUT + c)) * N_ + j0 + q * 16;
        *(uint4*)(dst)     = u0;
        *(uint4*)(dst + 8) = u1;
    }
}

// ---------------------------------------------------------------------------
// K0c: per-batch max of Wh2.
// ---------------------------------------------------------------------------
__global__ void k_maxwh2() {
    __shared__ float red[256];
    int b = blockIdx.x;
    float m = -1e30f;
    for (int i = threadIdx.x; i < N_; i += 256)
        m = fmaxf(m, g_Wh2[(size_t)b * N_ + i]);
    red[threadIdx.x] = m;
    __syncthreads();
    for (int s = 128; s > 0; s >>= 1) {
        if (threadIdx.x < s) red[threadIdx.x] = fmaxf(red[threadIdx.x], red[threadIdx.x + s]);
        __syncthreads();
    }
    if (threadIdx.x == 0) g_maxWh2[b] = red[0];
}

// ---------------------------------------------------------------------------
// K1: attention via warp-level mma.sync (HMMA), register accumulators.
// Grid: 512 blocks (8b x 16 i-tiles(128) x 4 j-splits), 256 threads (8 warps).
// Per 64-j chunk: phase1 builds fp16 P[128x64] + stages WhT[64x64] fp16 into
// padded smem; phase2: each warp does 4 k-steps x 8 n-blocks of m16n8k16.
// ---------------------------------------------------------------------------
#define PSTR 72   // padded row stride in halves (144 B): ldmatrix conflict-free

__global__ void __launch_bounds__(256) k_attn(const int* __restrict__ adj) {
    __shared__ __align__(16) __half Ps[128][PSTR];   // P  [i][j]
    __shared__ __align__(16) __half WT[64][PSTR];    // Wh [c][j]
    __shared__ float wh1s[128], Mr[128], ls[128];

    int tid  = threadIdx.x;
    int lane = tid & 31;
    int warp = tid >> 5;

    int split = blockIdx.x & (NSPLIT - 1);
    int tile  = blockIdx.x >> 2;
    int b  = tile >> 4;
    int i0 = (tile & 15) * 128;
    size_t rowbase = (size_t)b * N_ + i0;
    size_t bN = (size_t)b * N_;

    if (tid < 128) {
        float w1 = g_Wh1[rowbase + tid];
        wh1s[tid] = w1;
        float s = w1 + g_maxWh2[b];
        Mr[tid] = s > 0.f ? s : 0.2f * s;
    }

    // phase-1 mapping
    int cx = tid & 15, ry = tid >> 4;
    int tjx = cx * 4;
    float lp[8];
#pragma unroll
    for (int k = 0; k < 8; k++) lp[k] = 0.f;

    // mma accumulators: D[16 x 64] per warp -> 8 n-blocks x 4 floats
    float acc[8][4];
#pragma unroll
    for (int nb = 0; nb < 8; nb++)
#pragma unroll
        for (int q = 0; q < 4; q++) acc[nb][q] = 0.f;

    // ldmatrix addresses (constant across chunks)
    int iw = warp * 16;
    // A: row = iw + (lane&7) + 8*((lane>>3)&1); col base += 8*((lane>>4)&1)
    uint32_t a_addr_base = smem_u32(&Ps[iw + (lane & 7) + 8 * ((lane >> 3) & 1)]
                                      [8 * ((lane >> 4) & 1)]);
    // B (x4, two n-blocks): row = nb2*16 + 8*((lane>>4)&1) + (lane&7); col += 8*((lane>>3)&1)
    uint32_t b_addr_base = smem_u32(&WT[8 * ((lane >> 4) & 1) + (lane & 7)]
                                      [8 * ((lane >> 3) & 1)]);

    int jt0 = split * JCHUNK;

    for (int ch = 0; ch < NCHUNK; ch++) {
        int jt = jt0 + ch * 64;
        __syncthreads();   // previous phase2 reads done

        // ---- stage WhT tile [64c x 64j] fp16 ----
#pragma unroll
        for (int l = 0; l < 2; l++) {
            int idx = l * 256 + tid;
            int row = idx >> 3, seg = idx & 7;
            uint4 v = *(const uint4*)(g_WhT + ((size_t)(b * FOUT + row)) * N_ + jt + seg * 8);
            *(uint4*)&WT[row][seg * 8] = v;
        }

        // ---- phase 1: P tile [128 x 64] fp16 ----
        float4 w2v = *(const float4*)&g_Wh2[bN + jt + tjx];
#pragma unroll
        for (int k = 0; k < 8; k++) {
            int row = ry + 16 * k;
            int4 av = *(const int4*)&adj[(rowbase + row) * N_ + jt + tjx];
            float w1v = wh1s[row], mrv = Mr[row];
            float s, p0, p1, p2, p3;
            s = w1v + w2v.x; s = s > 0.f ? s : 0.2f * s;
            p0 = (av.x > 0) ? __expf(s - mrv) : 0.f;
            s = w1v + w2v.y; s = s > 0.f ? s : 0.2f * s;
            p1 = (av.y > 0) ? __expf(s - mrv) : 0.f;
            s = w1v + w2v.z; s = s > 0.f ? s : 0.2f * s;
            p2 = (av.z > 0) ? __expf(s - mrv) : 0.f;
            s = w1v + w2v.w; s = s > 0.f ? s : 0.2f * s;
            p3 = (av.w > 0) ? __expf(s - mrv) : 0.f;
            __half2 h0 = __floats2half2_rn(p0, p1);
            __half2 h1 = __floats2half2_rn(p2, p3);
            // denominator from ROUNDED values (consistent with MMA numerator)
            float2 f0 = __half22float2(h0), f1 = __half22float2(h1);
            lp[k] += (f0.x + f0.y) + (f1.x + f1.y);
            *(uint2*)&Ps[row][tjx] = make_uint2(*(uint32_t*)&h0, *(uint32_t*)&h1);
        }
        __syncthreads();

        // ---- phase 2: D += P @ WT^T via mma.sync m16n8k16 ----
#pragma unroll
        for (int k = 0; k < 4; k++) {
            uint32_t a0, a1, a2, a3;
            asm volatile("ldmatrix.sync.aligned.m8n8.x4.shared.b16 {%0,%1,%2,%3}, [%4];"
                         : "=r"(a0), "=r"(a1), "=r"(a2), "=r"(a3)
                         : "r"(a_addr_base + k * 32));
#pragma unroll
            for (int nb2 = 0; nb2 < 4; nb2++) {
                uint32_t b0, b1, b2, b3;
                asm volatile("ldmatrix.sync.aligned.m8n8.x4.shared.b16 {%0,%1,%2,%3}, [%4];"
                             : "=r"(b0), "=r"(b1), "=r"(b2), "=r"(b3)
                             : "r"(b_addr_base + nb2 * 16 * (PSTR * 2) + k * 32));
                float* c0 = acc[nb2 * 2];
                float* c1 = acc[nb2 * 2 + 1];
                asm volatile("mma.sync.aligned.m16n8k16.row.col.f32.f16.f16.f32 "
                             "{%0,%1,%2,%3}, {%4,%5,%6,%7}, {%8,%9}, {%0,%1,%2,%3};"
                             : "+f"(c0[0]), "+f"(c0[1]), "+f"(c0[2]), "+f"(c0[3])
                             : "r"(a0), "r"(a1), "r"(a2), "r"(a3), "r"(b0), "r"(b1));
                asm volatile("mma.sync.aligned.m16n8k16.row.col.f32.f16.f16.f32 "
                             "{%0,%1,%2,%3}, {%4,%5,%6,%7}, {%8,%9}, {%0,%1,%2,%3};"
                             : "+f"(c1[0]), "+f"(c1[1]), "+f"(c1[2]), "+f"(c1[3])
                             : "r"(a0), "r"(a1), "r"(a2), "r"(a3), "r"(b2), "r"(b3));
            }
        }
    }

    // ---- denominators ----
#pragma unroll
    for (int k = 0; k < 8; k++) {
        float v = lp[k];
        v += __shfl_xor_sync(0xffffffffu, v, 1);
        v += __shfl_xor_sync(0xffffffffu, v, 2);
        v += __shfl_xor_sync(0xffffffffu, v, 4);
        v += __shfl_xor_sync(0xffffffffu, v, 8);
        if ((tid & 15) == 0) ls[ry + 16 * k] = v;
    }
    __syncthreads();

    // ---- store partials ----
    size_t abase = (size_t)split * (B_ * N_) + rowbase;
    if (tid < 128) g_lpart[abase + tid] = ls[tid];

    int gid = lane >> 2, tig = lane & 3;
#pragma unroll
    for (int nb = 0; nb < 8; nb++) {
        int col = nb * 8 + tig * 2;
        float2 v0 = {acc[nb][0], acc[nb][1]};
        float2 v1 = {acc[nb][2], acc[nb][3]};
        *(float2*)&g_accp[(abase + iw + gid) * FOUT + col]     = v0;
        *(float2*)&g_accp[(abase + iw + gid + 8) * FOUT + col] = v1;
    }
}

// ---------------------------------------------------------------------------
// K2: combine split partials, normalize, ELU, store.
// ---------------------------------------------------------------------------
__global__ void k_final(float* __restrict__ out) {
    int t = blockIdx.x * 256 + threadIdx.x;
    int row = t >> 4;
    int c4 = (t & 15) * 4;

    float l = 0.f;
    float4 s = {0.f, 0.f, 0.f, 0.f};
#pragma unroll
    for (int sp = 0; sp < NSPLIT; sp++) {
        size_t base = (size_t)sp * (B_ * N_) + row;
        l += g_lpart[base];
        float4 v = *(const float4*)&g_accp[base * FOUT + c4];
        s.x += v.x; s.y += v.y; s.z += v.z; s.w += v.w;
    }
    float inv = 1.f / l;
    float v;
    float4 o;
    v = s.x * inv; o.x = v > 0.f ? v : expm1f(v);
    v = s.y * inv; o.y = v > 0.f ? v : expm1f(v);
    v = s.z * inv; o.z = v > 0.f ? v : expm1f(v);
    v = s.w * inv; o.w = v > 0.f ? v : expm1f(v);
    *(float4*)&out[(size_t)row * FOUT + c4] = o;
}

// ---------------------------------------------------------------------------
extern "C" void kernel_launch(void* const* d_in, const int* in_sizes, int n_in,
                              void* d_out, int out_size) {
    const float* h   = (const float*)d_in[0];
    const int*   adj = (const int*)d_in[1];
    const float* W   = (const float*)d_in[2];
    const float* a   = (const float*)d_in[3];
    float* out = (float*)d_out;

    k_gemm1<<<(B_ * N_) / 64, 256>>>(h, W, a);
    k_maxwh2<<<B_, 256>>>();
    k_attn<<<(B_ * N_ / 128) * NSPLIT, 256>>>(adj);
    k_final<<<(B_ * N_ * FOUT) / 1024, 256>>>(out);
}

// round 9
// speedup vs baseline: 2.3299x; 1.2047x over previous
#include <cuda_runtime.h>
#include <cuda_fp16.h>
#include <cstdint>

// Problem constants
#define B_  8
#define N_  2048
#define FIN 256
#define FOUT 64
#define NSPLIT 4
#define JCHUNK (N_ / NSPLIT)   // 512
#define NCHUNK (JCHUNK / 64)   // 8
#define NW     (N_ / 32)       // 64 bit-words per row

// Scratch (device globals: allocation-free)
__device__ __half    g_WhT[B_ * FOUT * N_];           // [b][c][j] fp16, 2 MB
__device__ float     g_Wh1[B_ * N_];
__device__ float     g_Wh2[B_ * N_];
__device__ float     g_maxWh2[B_];
__device__ float     g_accp[NSPLIT * B_ * N_ * FOUT]; // partial numerators
__device__ float     g_lpart[NSPLIT * B_ * N_];       // partial denominators
__device__ uint32_t  g_adjbits[B_ * N_ * NW];         // 4.2 MB packed adjacency

__device__ __forceinline__ uint32_t smem_u32(const void* p) {
    uint32_t a;
    asm("{ .reg .u64 t; cvta.to.shared.u64 t, %1; cvt.u32.u64 %0, t; }" : "=r"(a) : "l"(p));
    return a;
}

// ---------------------------------------------------------------------------
// KP: pack adj (int32 0/1) into bitmask. Pure streaming: int4 loads,
// nibble shfl-OR packing. Each warp-iter: 128 ints -> 4 words.
// Grid: 2048 blocks x 256 threads; each warp does 16 iters (8 KB adj).
// ---------------------------------------------------------------------------
__global__ void k_pack(const int* __restrict__ adj) {
    int lane = threadIdx.x & 31;
    int gw = blockIdx.x * 8 + (threadIdx.x >> 5);       // global warp id
    size_t ibase = (size_t)gw * 2048;                   // int index (16 iters x 128)

#pragma unroll 4
    for (int it = 0; it < 16; it++) {
        size_t idx = ibase + it * 128 + lane * 4;
        int4 v = *(const int4*)(adj + idx);
        uint32_t nib = (v.x > 0 ? 1u : 0u) | (v.y > 0 ? 2u : 0u)
                     | (v.z > 0 ? 4u : 0u) | (v.w > 0 ? 8u : 0u);
        nib <<= 4 * (lane & 7);
        nib |= __shfl_xor_sync(0xffffffffu, nib, 1);
        nib |= __shfl_xor_sync(0xffffffffu, nib, 2);
        nib |= __shfl_xor_sync(0xffffffffu, nib, 4);
        if ((lane & 7) == 0)
            g_adjbits[(ibase + it * 128) / 32 + (lane >> 3)] = nib;
    }
}

// ---------------------------------------------------------------------------
// K0: Wh = h @ W; epilogue computes Wh1/Wh2 and writes transposed fp16 WhT.
// Grid: 256 blocks x 256 threads, 64 rows per block.
// ---------------------------------------------------------------------------
__global__ void k_gemm1(const float* __restrict__ h, const float* __restrict__ W,
                        const float* __restrict__ a) {
    __shared__ __align__(16) float hs[64][68];
    __shared__ __align__(16) float Wst[64][68];
    __shared__ float as[128];

    int tid = threadIdx.x;
    int tx = tid & 63, ty = tid >> 6;
    int r0 = blockIdx.x * 64;

    if (tid < 128) as[tid] = a[tid];

    float acc[16];
#pragma unroll
    for (int i = 0; i < 16; i++) acc[i] = 0.f;

    for (int kt = 0; kt < 4; kt++) {
        __syncthreads();
#pragma unroll
        for (int l = 0; l < 16; l++) {
            int idx = l * 256 + tid;
            int r = idx >> 6, kk = idx & 63;
            hs[r][kk] = h[(size_t)(r0 + r) * FIN + kt * 64 + kk];
        }
#pragma unroll
        for (int l = 0; l < 16; l++) {
            int idx = l * 256 + tid;
            int kk = idx >> 6, c = idx & 63;
            Wst[c][kk] = W[(size_t)(kt * 64 + kk) * FOUT + c];
        }
        __syncthreads();

        for (int kk = 0; kk < 64; kk += 4) {
            float4 wv = *(const float4*)&Wst[tx][kk];
#pragma unroll
            for (int i = 0; i < 16; i++) {
                float4 hv = *(const float4*)&hs[ty + 4 * i][kk];
                acc[i] += hv.x * wv.x;
                acc[i] += hv.y * wv.y;
                acc[i] += hv.z * wv.z;
                acc[i] += hv.w * wv.w;
            }
        }
    }

    __syncthreads();
#pragma unroll
    for (int i = 0; i < 16; i++) hs[ty + 4 * i][tx] = acc[i];
    __syncthreads();

    int b  = r0 >> 11;        // batch
    int j0 = r0 & 2047;       // j offset within batch

    // Wh1/Wh2: 4 threads per row
    {
        int row = tid >> 2, q = tid & 3;
        float s1 = 0.f, s2 = 0.f;
#pragma unroll
        for (int i = 0; i < 16; i++) {
            int c = q * 16 + i;
            float v = hs[row][c];
            s1 += v * as[c];
            s2 += v * as[64 + c];
        }
        s1 += __shfl_xor_sync(0xffffffffu, s1, 1);
        s1 += __shfl_xor_sync(0xffffffffu, s1, 2);
        s2 += __shfl_xor_sync(0xffffffffu, s2, 1);
        s2 += __shfl_xor_sync(0xffffffffu, s2, 2);
        if (q == 0) {
            g_Wh1[r0 + row] = s1;
            g_Wh2[r0 + row] = s2;
        }
    }

    // WhT[b][c][j0..j0+63] fp16 (transpose from hs)
    {
        int c = tid >> 2, q = tid & 3;   // 64 cols x 4 j-quarters
        __half2 hh[8];
#pragma unroll
        for (int i = 0; i < 8; i++)
            hh[i] = __floats2half2_rn(hs[q * 16 + 2 * i][c], hs[q * 16 + 2 * i + 1][c]);
        uint4 u0 = make_uint4(*(uint32_t*)&hh[0], *(uint32_t*)&hh[1],
                              *(uint32_t*)&hh[2], *(uint32_t*)&hh[3]);
        uint4 u1 = make_uint4(*(uint32_t*)&hh[4], *(uint32_t*)&hh[5],
                              *(uint32_t*)&hh[6], *(uint32_t*)&hh[7]);
        __half* dst = g_WhT + ((size_t)(b * FOUT + c)) * N_ + j0 + q * 16;
        *(uint4*)(dst)     = u0;
        *(uint4*)(dst + 8) = u1;
    }
}

// ---------------------------------------------------------------------------
// K0c: per-batch max of Wh2.
// ---------------------------------------------------------------------------
__global__ void k_maxwh2() {
    __shared__ float red[256];
    int b = blockIdx.x;
    float m = -1e30f;
    for (int i = threadIdx.x; i < N_; i += 256)
        m = fmaxf(m, g_Wh2[(size_t)b * N_ + i]);
    red[threadIdx.x] = m;
    __syncthreads();
    for (int s = 128; s > 0; s >>= 1) {
        if (threadIdx.x < s) red[threadIdx.x] = fmaxf(red[threadIdx.x], red[threadIdx.x + s]);
        __syncthreads();
    }
    if (threadIdx.x == 0) g_maxWh2[b] = red[0];
}

// ---------------------------------------------------------------------------
// K1: attention via warp-level mma.sync (HMMA), register accumulators.
// Grid: 512 blocks (8b x 16 i-tiles(128) x 4 j-splits), 256 threads (8 warps).
// Phase1 reads the PACKED adjacency bitmask (L2-resident, 4.2 MB total).
// ---------------------------------------------------------------------------
#define PSTR 72   // padded row stride in halves (144 B): ldmatrix conflict-free

__global__ void __launch_bounds__(256) k_attn() {
    __shared__ __align__(16) __half Ps[128][PSTR];   // P  [i][j]
    __shared__ __align__(16) __half WT[64][PSTR];    // Wh [c][j]
    __shared__ float wh1s[128], Mr[128], ls[128];

    int tid  = threadIdx.x;
    int lane = tid & 31;
    int warp = tid >> 5;

    int split = blockIdx.x & (NSPLIT - 1);
    int tile  = blockIdx.x >> 2;
    int b  = tile >> 4;
    int i0 = (tile & 15) * 128;
    size_t rowbase = (size_t)b * N_ + i0;
    size_t bN = (size_t)b * N_;

    if (tid < 128) {
        float w1 = g_Wh1[rowbase + tid];
        wh1s[tid] = w1;
        float s = w1 + g_maxWh2[b];
        Mr[tid] = s > 0.f ? s : 0.2f * s;
    }

    // phase-1 mapping
    int cx = tid & 15, ry = tid >> 4;
    int tjx = cx * 4;
    float lp[8];
#pragma unroll
    for (int k = 0; k < 8; k++) lp[k] = 0.f;

    // mma accumulators: D[16 x 64] per warp -> 8 n-blocks x 4 floats
    float acc[8][4];
#pragma unroll
    for (int nb = 0; nb < 8; nb++)
#pragma unroll
        for (int q = 0; q < 4; q++) acc[nb][q] = 0.f;

    // ldmatrix addresses (constant across chunks)
    int iw = warp * 16;
    uint32_t a_addr_base = smem_u32(&Ps[iw + (lane & 7) + 8 * ((lane >> 3) & 1)]
                                      [8 * ((lane >> 4) & 1)]);
    uint32_t b_addr_base = smem_u32(&WT[8 * ((lane >> 4) & 1) + (lane & 7)]
                                      [8 * ((lane >> 3) & 1)]);

    int jt0 = split * JCHUNK;
    const uint32_t* bitbase = g_adjbits + rowbase * NW;
    int bshift = tjx & 31;

    for (int ch = 0; ch < NCHUNK; ch++) {
        int jt = jt0 + ch * 64;
        __syncthreads();   // previous phase2 reads done

        // ---- stage WhT tile [64c x 64j] fp16 ----
#pragma unroll
        for (int l = 0; l < 2; l++) {
            int idx = l * 256 + tid;
            int row = idx >> 3, seg = idx & 7;
            uint4 v = *(const uint4*)(g_WhT + ((size_t)(b * FOUT + row)) * N_ + jt + seg * 8);
            *(uint4*)&WT[row][seg * 8] = v;
        }

        // ---- phase 1: P tile [128 x 64] fp16 from bitmask ----
        float4 w2v = *(const float4*)&g_Wh2[bN + jt + tjx];
        int wcol = (jt + tjx) >> 5;
#pragma unroll
        for (int k = 0; k < 8; k++) {
            int row = ry + 16 * k;
            uint32_t bits = bitbase[row * NW + wcol] >> bshift;
            float w1v = wh1s[row], mrv = Mr[row];
            float s, p0, p1, p2, p3;
            s = w1v + w2v.x; s = s > 0.f ? s : 0.2f * s;
            p0 = (bits & 1u) ? __expf(s - mrv) : 0.f;
            s = w1v + w2v.y; s = s > 0.f ? s : 0.2f * s;
            p1 = (bits & 2u) ? __expf(s - mrv) : 0.f;
            s = w1v + w2v.z; s = s > 0.f ? s : 0.2f * s;
            p2 = (bits & 4u) ? __expf(s - mrv) : 0.f;
            s = w1v + w2v.w; s = s > 0.f ? s : 0.2f * s;
            p3 = (bits & 8u) ? __expf(s - mrv) : 0.f;
            __half2 h0 = __floats2half2_rn(p0, p1);
            __half2 h1 = __floats2half2_rn(p2, p3);
            // denominator from ROUNDED values (consistent with MMA numerator)
            float2 f0 = __half22float2(h0), f1 = __half22float2(h1);
            lp[k] += (f0.x + f0.y) + (f1.x + f1.y);
            *(uint2*)&Ps[row][tjx] = make_uint2(*(uint32_t*)&h0, *(uint32_t*)&h1);
        }
        __syncthreads();

        // ---- phase 2: D += P @ WT^T via mma.sync m16n8k16 ----
#pragma unroll
        for (int k = 0; k < 4; k++) {
            uint32_t a0, a1, a2, a3;
            asm volatile("ldmatrix.sync.aligned.m8n8.x4.shared.b16 {%0,%1,%2,%3}, [%4];"
                         : "=r"(a0), "=r"(a1), "=r"(a2), "=r"(a3)
                         : "r"(a_addr_base + k * 32));
#pragma unroll
            for (int nb2 = 0; nb2 < 4; nb2++) {
                uint32_t b0, b1, b2, b3;
                asm volatile("ldmatrix.sync.aligned.m8n8.x4.shared.b16 {%0,%1,%2,%3}, [%4];"
                             : "=r"(b0), "=r"(b1), "=r"(b2), "=r"(b3)
                             : "r"(b_addr_base + nb2 * 16 * (PSTR * 2) + k * 32));
                float* c0 = acc[nb2 * 2];
                float* c1 = acc[nb2 * 2 + 1];
                asm volatile("mma.sync.aligned.m16n8k16.row.col.f32.f16.f16.f32 "
                             "{%0,%1,%2,%3}, {%4,%5,%6,%7}, {%8,%9}, {%0,%1,%2,%3};"
                             : "+f"(c0[0]), "+f"(c0[1]), "+f"(c0[2]), "+f"(c0[3])
                             : "r"(a0), "r"(a1), "r"(a2), "r"(a3), "r"(b0), "r"(b1));
                asm volatile("mma.sync.aligned.m16n8k16.row.col.f32.f16.f16.f32 "
                             "{%0,%1,%2,%3}, {%4,%5,%6,%7}, {%8,%9}, {%0,%1,%2,%3};"
                             : "+f"(c1[0]), "+f"(c1[1]), "+f"(c1[2]), "+f"(c1[3])
                             : "r"(a0), "r"(a1), "r"(a2), "r"(a3), "r"(b2), "r"(b3));
            }
        }
    }

    // ---- denominators ----
#pragma unroll
    for (int k = 0; k < 8; k++) {
        float v = lp[k];
        v += __shfl_xor_sync(0xffffffffu, v, 1);
        v += __shfl_xor_sync(0xffffffffu, v, 2);
        v += __shfl_xor_sync(0xffffffffu, v, 4);
        v += __shfl_xor_sync(0xffffffffu, v, 8);
        if ((tid & 15) == 0) ls[ry + 16 * k] = v;
    }
    __syncthreads();

    // ---- store partials ----
    size_t abase = (size_t)split * (B_ * N_) + rowbase;
    if (tid < 128) g_lpart[abase + tid] = ls[tid];

    int gid = lane >> 2, tig = lane & 3;
#pragma unroll
    for (int nb = 0; nb < 8; nb++) {
        int col = nb * 8 + tig * 2;
        float2 v0 = {acc[nb][0], acc[nb][1]};
        float2 v1 = {acc[nb][2], acc[nb][3]};
        *(float2*)&g_accp[(abase + iw + gid) * FOUT + col]     = v0;
        *(float2*)&g_accp[(abase + iw + gid + 8) * FOUT + col] = v1;
    }
}

// ---------------------------------------------------------------------------
// K2: combine split partials, normalize, ELU, store.
// ---------------------------------------------------------------------------
__global__ void k_final(float* __restrict__ out) {
    int t = blockIdx.x * 256 + threadIdx.x;
    int row = t >> 4;
    int c4 = (t & 15) * 4;

    float l = 0.f;
    float4 s = {0.f, 0.f, 0.f, 0.f};
#pragma unroll
    for (int sp = 0; sp < NSPLIT; sp++) {
        size_t base = (size_t)sp * (B_ * N_) + row;
        l += g_lpart[base];
        float4 v = *(const float4*)&g_accp[base * FOUT + c4];
        s.x += v.x; s.y += v.y; s.z += v.z; s.w += v.w;
    }
    float inv = 1.f / l;
    float v;
    float4 o;
    v = s.x * inv; o.x = v > 0.f ? v : expm1f(v);
    v = s.y * inv; o.y = v > 0.f ? v : expm1f(v);
    v = s.z * inv; o.z = v > 0.f ? v : expm1f(v);
    v = s.w * inv; o.w = v > 0.f ? v : expm1f(v);
    *(float4*)&out[(size_t)row * FOUT + c4] = o;
}

// ---------------------------------------------------------------------------
extern "C" void kernel_launch(void* const* d_in, const int* in_sizes, int n_in,
                              void* d_out, int out_size) {
    const float* h   = (const float*)d_in[0];
    const int*   adj = (const int*)d_in[1];
    const float* W   = (const float*)d_in[2];
    const float* a   = (const float*)d_in[3];
    float* out = (float*)d_out;

    k_pack<<<2048, 256>>>(adj);
    k_gemm1<<<(B_ * N_) / 64, 256>>>(h, W, a);
    k_maxwh2<<<B_, 256>>>();
    k_attn<<<(B_ * N_ / 128) * NSPLIT, 256>>>();
    k_final<<<(B_ * N_ * FOUT) / 1024, 256>>>(out);
}

// round 14
// speedup vs baseline: 2.6755x; 1.1483x over previous
#include <cuda_runtime.h>
#include <cuda_fp16.h>
#include <cstdint>

// Problem constants
#define B_  8
#define N_  2048
#define FIN 256
#define FOUT 64
#define NSPLIT 4
#define JCHUNK (N_ / NSPLIT)   // 512
#define NCHUNK (JCHUNK / 64)   // 8
#define NW     (N_ / 32)       // 64 bit-words per row
#define ITILE  64              // i-rows per block (static smem < 48 KB)

// Scratch (device globals: allocation-free)
__device__ __half    g_WhT[B_ * FOUT * N_];           // [b][c][j] fp16, 2 MB
__device__ float     g_Wh1[B_ * N_];
__device__ float     g_Wh2[B_ * N_];
__device__ float     g_maxWh2[B_];
__device__ float     g_accp[NSPLIT * B_ * N_ * FOUT]; // partial numerators
__device__ float     g_lpart[NSPLIT * B_ * N_];       // partial denominators
__device__ uint32_t  g_adjbits[B_ * N_ * NW];         // 4.2 MB packed adjacency

__device__ __forceinline__ uint32_t smem_u32(const void* p) {
    uint32_t a;
    asm("{ .reg .u64 t; cvta.to.shared.u64 t, %1; cvt.u32.u64 %0, t; }" : "=r"(a) : "l"(p));
    return a;
}

// ---------------------------------------------------------------------------
// KP: pack adj (int32 0/1) into bitmask. Pure streaming.
// ---------------------------------------------------------------------------
__global__ void k_pack(const int* __restrict__ adj) {
    int lane = threadIdx.x & 31;
    int gw = blockIdx.x * 8 + (threadIdx.x >> 5);
    size_t ibase = (size_t)gw * 2048;

#pragma unroll 4
    for (int it = 0; it < 16; it++) {
        size_t idx = ibase + it * 128 + lane * 4;
        int4 v = *(const int4*)(adj + idx);
        uint32_t nib = (v.x > 0 ? 1u : 0u) | (v.y > 0 ? 2u : 0u)
                     | (v.z > 0 ? 4u : 0u) | (v.w > 0 ? 8u : 0u);
        nib <<= 4 * (lane & 7);
        nib |= __shfl_xor_sync(0xffffffffu, nib, 1);
        nib |= __shfl_xor_sync(0xffffffffu, nib, 2);
        nib |= __shfl_xor_sync(0xffffffffu, nib, 4);
        if ((lane & 7) == 0)
            g_adjbits[(ibase + it * 128) / 32 + (lane >> 3)] = nib;
    }
}

// ---------------------------------------------------------------------------
// K0: Wh = h @ W (f32x2 packed FMA); epilogue: Wh1/Wh2 + fp16 WhT transpose.
// Grid: 256 blocks x 256 threads, 64 rows per block.
// ---------------------------------------------------------------------------
__global__ void k_gemm1(const float* __restrict__ h, const float* __restrict__ W,
                        const float* __restrict__ a) {
    __shared__ __align__(16) float hs[64][68];
    __shared__ __align__(16) float Wst[64][68];
    __shared__ float as[128];

    int tid = threadIdx.x;
    int tx = tid & 63, ty = tid >> 6;
    int r0 = blockIdx.x * 64;

    if (tid < 128) as[tid] = a[tid];

    unsigned long long acc64[16];
#pragma unroll
    for (int i = 0; i < 16; i++) acc64[i] = 0ull;

    for (int kt = 0; kt < 4; kt++) {
        __syncthreads();
#pragma unroll
        for (int l = 0; l < 16; l++) {
            int idx = l * 256 + tid;
            int r = idx >> 6, kk = idx & 63;
            hs[r][kk] = h[(size_t)(r0 + r) * FIN + kt * 64 + kk];
        }
#pragma unroll
        for (int l = 0; l < 16; l++) {
            int idx = l * 256 + tid;
            int kk = idx >> 6, c = idx & 63;
            Wst[c][kk] = W[(size_t)(kt * 64 + kk) * FOUT + c];
        }
        __syncthreads();

        for (int kk = 0; kk < 64; kk += 4) {
            ulonglong2 wv = *(const ulonglong2*)&Wst[tx][kk];
#pragma unroll
            for (int i = 0; i < 16; i++) {
                ulonglong2 hv = *(const ulonglong2*)&hs[ty + 4 * i][kk];
                asm("fma.rn.f32x2 %0, %1, %2, %0;" : "+l"(acc64[i]) : "l"(hv.x), "l"(wv.x));
                asm("fma.rn.f32x2 %0, %1, %2, %0;" : "+l"(acc64[i]) : "l"(hv.y), "l"(wv.y));
            }
        }
    }

    float acc[16];
#pragma unroll
    for (int i = 0; i < 16; i++) {
        float lo, hi;
        asm("mov.b64 {%0, %1}, %2;" : "=f"(lo), "=f"(hi) : "l"(acc64[i]));
        acc[i] = lo + hi;
    }

    __syncthreads();
#pragma unroll
    for (int i = 0; i < 16; i++) hs[ty + 4 * i][tx] = acc[i];
    __syncthreads();

    int b  = r0 >> 11;        // batch
    int j0 = r0 & 2047;       // j offset within batch

    // Wh1/Wh2: 4 threads per row
    {
        int row = tid >> 2, q = tid & 3;
        float s1 = 0.f, s2 = 0.f;
#pragma unroll
        for (int i = 0; i < 16; i++) {
            int c = q * 16 + i;
            float v = hs[row][c];
            s1 += v * as[c];
            s2 += v * as[64 + c];
        }
        s1 += __shfl_xor_sync(0xffffffffu, s1, 1);
        s1 += __shfl_xor_sync(0xffffffffu, s1, 2);
        s2 += __shfl_xor_sync(0xffffffffu, s2, 1);
        s2 += __shfl_xor_sync(0xffffffffu, s2, 2);
        if (q == 0) {
            g_Wh1[r0 + row] = s1;
            g_Wh2[r0 + row] = s2;
        }
    }

    // WhT[b][c][j0..j0+63] fp16 (transpose from hs)
    {
        int c = tid >> 2, q = tid & 3;
        __half2 hh[8];
#pragma unroll
        for (int i = 0; i < 8; i++)
            hh[i] = __floats2half2_rn(hs[q * 16 + 2 * i][c], hs[q * 16 + 2 * i + 1][c]);
        uint4 u0 = make_uint4(*(uint32_t*)&hh[0], *(uint32_t*)&hh[1],
                              *(uint32_t*)&hh[2], *(uint32_t*)&hh[3]);
        uint4 u1 = make_uint4(*(uint32_t*)&hh[4], *(uint32_t*)&hh[5],
                              *(uint32_t*)&hh[6], *(uint32_t*)&hh[7]);
        __half* dst = g_WhT + ((size_t)(b * FOUT + c)) * N_ + j0 + q * 16;
        *(uint4*)(dst)     = u0;
        *(uint4*)(dst + 8) = u1;
    }
}

// ---------------------------------------------------------------------------
// K0c: per-batch max of Wh2.
// ---------------------------------------------------------------------------
__global__ void k_maxwh2() {
    __shared__ float red[256];
    int b = blockIdx.x;
    float m = -1e30f;
    for (int i = threadIdx.x; i < N_; i += 256)
        m = fmaxf(m, g_Wh2[(size_t)b * N_ + i]);
    red[threadIdx.x] = m;
    __syncthreads();
    for (int s = 128; s > 0; s >>= 1) {
        if (threadIdx.x < s) red[threadIdx.x] = fmaxf(red[threadIdx.x], red[threadIdx.x + s]);
        __syncthreads();
    }
    if (threadIdx.x == 0) g_maxWh2[b] = red[0];
}

// ---------------------------------------------------------------------------
// K1: attention, HMMA + DOUBLE-BUFFERED pipeline (one barrier per chunk).
// STATIC smem: 39.7 KB (< 48 KB). i-tile = 64 rows.
// Grid: 1024 blocks (8b x 32 i-tiles(64) x 4 j-splits), 256 threads (8 warps).
// Warp w: rows (w&3)*16..+15, cols (w>>2)*32..+31 (4 n-blocks of 8).
// ---------------------------------------------------------------------------
#define PSTR 72   // padded row stride in halves (144 B): ldmatrix conflict-free

__global__ void __launch_bounds__(256) k_attn() {
    __shared__ __align__(16) __half Ps[2][ITILE][PSTR];   // 18432 B
    __shared__ __align__(16) __half WT[2][64][PSTR];      // 18432 B
    __shared__ float wh1s[ITILE], Mr[ITILE], ls[ITILE];
    __shared__ __align__(16) float wh2s[JCHUNK];          // 2048 B

    int tid  = threadIdx.x;
    int lane = tid & 31;
    int warp = tid >> 5;

    int split = blockIdx.x & (NSPLIT - 1);
    int tile  = blockIdx.x >> 2;
    int b  = tile >> 5;
    int i0 = (tile & 31) * ITILE;
    size_t rowbase = (size_t)b * N_ + i0;
    int jt0 = split * JCHUNK;

    if (tid < ITILE) {
        float w1 = g_Wh1[rowbase + tid];
        wh1s[tid] = w1;
        float s = w1 + g_maxWh2[b];
        Mr[tid] = s > 0.f ? s : 0.2f * s;
    }
    for (int i = tid; i < JCHUNK; i += 256)
        wh2s[i] = g_Wh2[(size_t)b * N_ + jt0 + i];

    // phase-1 mapping: 16 row-slots x 16 j-groups
    int cx = tid & 15, ry = tid >> 4;
    int tjx = cx * 4;
    float lp[4] = {0.f, 0.f, 0.f, 0.f};

    // mma accumulators: 16 rows x 32 cols per warp -> 4 n-blocks x 4 floats
    float acc[4][4];
#pragma unroll
    for (int nb = 0; nb < 4; nb++)
#pragma unroll
        for (int q = 0; q < 4; q++) acc[nb][q] = 0.f;

    const uint32_t* bitbase = g_adjbits + rowbase * NW;
    int bshift = tjx & 31;

    // producer: stage WT + build P for chunk ch into buffer bf
    auto produce = [&](int ch, int bf) {
        int jt = jt0 + ch * 64;
#pragma unroll
        for (int l = 0; l < 2; l++) {
            int idx = l * 256 + tid;
            int row = idx >> 3, seg = idx & 7;
            uint4 v = *(const uint4*)(g_WhT + ((size_t)(b * FOUT + row)) * N_ + jt + seg * 8);
            *(uint4*)&WT[bf][row][seg * 8] = v;
        }
        float4 w2v = *(const float4*)&wh2s[ch * 64 + tjx];
        int wcol = (jt + tjx) >> 5;
#pragma unroll
        for (int k = 0; k < 4; k++) {
            int row = ry + 16 * k;
            uint32_t bits = bitbase[row * NW + wcol] >> bshift;
            float w1v = wh1s[row], mrv = Mr[row];
            float s, p0, p1, p2, p3;
            s = w1v + w2v.x; s = s > 0.f ? s : 0.2f * s;
            p0 = (bits & 1u) ? __expf(s - mrv) : 0.f;
            s = w1v + w2v.y; s = s > 0.f ? s : 0.2f * s;
            p1 = (bits & 2u) ? __expf(s - mrv) : 0.f;
            s = w1v + w2v.z; s = s > 0.f ? s : 0.2f * s;
            p2 = (bits & 4u) ? __expf(s - mrv) : 0.f;
            s = w1v + w2v.w; s = s > 0.f ? s : 0.2f * s;
            p3 = (bits & 8u) ? __expf(s - mrv) : 0.f;
            __half2 h0 = __floats2half2_rn(p0, p1);
            __half2 h1 = __floats2half2_rn(p2, p3);
            // denominator from ROUNDED values (consistent with MMA numerator)
            float2 f0 = __half22float2(h0), f1 = __half22float2(h1);
            lp[k] += (f0.x + f0.y) + (f1.x + f1.y);
            *(uint2*)&Ps[bf][row][tjx] = make_uint2(*(uint32_t*)&h0, *(uint32_t*)&h1);
        }
    };

    // ldmatrix base addresses (buffer 0)
    int iw  = (warp & 3) * 16;   // row base
    int nco = (warp >> 2) * 32;  // col base
    uint32_t a_base = smem_u32(&Ps[0][iw + (lane & 7) + 8 * ((lane >> 3) & 1)]
                                    [8 * ((lane >> 4) & 1)]);
    uint32_t b_base = smem_u32(&WT[0][nco + 8 * ((lane >> 4) & 1) + (lane & 7)]
                                    [8 * ((lane >> 3) & 1)]);
    const uint32_t PSZ = ITILE * PSTR * 2;   // bytes per Ps buffer
    const uint32_t WSZ = 64 * PSTR * 2;      // bytes per WT buffer

    // RACE FIX (R13 NaN): order wh1s/Mr/wh2s init writes before produce(0)
    // reads them cross-thread. R9's loop-top barrier did this implicitly;
    // the pipelined restructure lost it.
    __syncthreads();

    produce(0, 0);
    __syncthreads();

    for (int ch = 0; ch < NCHUNK; ch++) {
        int cur = ch & 1;
        if (ch + 1 < NCHUNK) produce(ch + 1, cur ^ 1);

        // consume buffer cur: D += P @ WT^T via mma.sync m16n8k16
        uint32_t aab = a_base + cur * PSZ;
        uint32_t bbb = b_base + cur * WSZ;
#pragma unroll
        for (int k = 0; k < 4; k++) {
            uint32_t a0, a1, a2, a3;
            asm volatile("ldmatrix.sync.aligned.m8n8.x4.shared.b16 {%0,%1,%2,%3}, [%4];"
                         : "=r"(a0), "=r"(a1), "=r"(a2), "=r"(a3)
                         : "r"(aab + k * 32));
#pragma unroll
            for (int nb2 = 0; nb2 < 2; nb2++) {
                uint32_t b0, b1, b2, b3;
                asm volatile("ldmatrix.sync.aligned.m8n8.x4.shared.b16 {%0,%1,%2,%3}, [%4];"
                             : "=r"(b0), "=r"(b1), "=r"(b2), "=r"(b3)
                             : "r"(bbb + nb2 * 16 * (PSTR * 2) + k * 32));
                float* c0 = acc[nb2 * 2];
                float* c1 = acc[nb2 * 2 + 1];
                asm volatile("mma.sync.aligned.m16n8k16.row.col.f32.f16.f16.f32 "
                             "{%0,%1,%2,%3}, {%4,%5,%6,%7}, {%8,%9}, {%0,%1,%2,%3};"
                             : "+f"(c0[0]), "+f"(c0[1]), "+f"(c0[2]), "+f"(c0[3])
                             : "r"(a0), "r"(a1), "r"(a2), "r"(a3), "r"(b0), "r"(b1));
                asm volatile("mma.sync.aligned.m16n8k16.row.col.f32.f16.f16.f32 "
                             "{%0,%1,%2,%3}, {%4,%5,%6,%7}, {%8,%9}, {%0,%1,%2,%3};"
                             : "+f"(c1[0]), "+f"(c1[1]), "+f"(c1[2]), "+f"(c1[3])
                             : "r"(a0), "r"(a1), "r"(a2), "r"(a3), "r"(b2), "r"(b3));
            }
        }
        __syncthreads();
    }

    // ---- denominators (16-lane groups) ----
#pragma unroll
    for (int k = 0; k < 4; k++) {
        float v = lp[k];
        v += __shfl_xor_sync(0xffffffffu, v, 1);
        v += __shfl_xor_sync(0xffffffffu, v, 2);
        v += __shfl_xor_sync(0xffffffffu, v, 4);
        v += __shfl_xor_sync(0xffffffffu, v, 8);
        if ((tid & 15) == 0) ls[ry + 16 * k] = v;
    }
    __syncthreads();

    // ---- store partials ----
    size_t abase = (size_t)split * (B_ * N_) + rowbase;
    if (tid < ITILE) g_lpart[abase + tid] = ls[tid];

    int gid = lane >> 2, tig = lane & 3;
#pragma unroll
    for (int nb = 0; nb < 4; nb++) {
        int col = nco + nb * 8 + tig * 2;
        float2 v0 = {acc[nb][0], acc[nb][1]};
        float2 v1 = {acc[nb][2], acc[nb][3]};
        *(float2*)&g_accp[(abase + iw + gid) * FOUT + col]     = v0;
        *(float2*)&g_accp[(abase + iw + gid + 8) * FOUT + col] = v1;
    }
}

// ---------------------------------------------------------------------------
// K2: combine split partials, normalize, ELU, store.
// ---------------------------------------------------------------------------
__global__ void k_final(float* __restrict__ out) {
    int t = blockIdx.x * 256 + threadIdx.x;
    int row = t >> 4;
    int c4 = (t & 15) * 4;

    float l = 0.f;
    float4 s = {0.f, 0.f, 0.f, 0.f};
#pragma unroll
    for (int sp = 0; sp < NSPLIT; sp++) {
        size_t base = (size_t)sp * (B_ * N_) + row;
        l += g_lpart[base];
        float4 v = *(const float4*)&g_accp[base * FOUT + c4];
        s.x += v.x; s.y += v.y; s.z += v.z; s.w += v.w;
    }
    float inv = 1.f / l;
    float v;
    float4 o;
    v = s.x * inv; o.x = v > 0.f ? v : expm1f(v);
    v = s.y * inv; o.y = v > 0.f ? v : expm1f(v);
    v = s.z * inv; o.z = v > 0.f ? v : expm1f(v);
    v = s.w * inv; o.w = v > 0.f ? v : expm1f(v);
    *(float4*)&out[(size_t)row * FOUT + c4] = o;
}

// ---------------------------------------------------------------------------
extern "C" void kernel_launch(void* const* d_in, const int* in_sizes, int n_in,
                              void* d_out, int out_size) {
    const float* h   = (const float*)d_in[0];
    const int*   adj = (const int*)d_in[1];
    const float* W   = (const float*)d_in[2];
    const float* a   = (const float*)d_in[3];
    float* out = (float*)d_out;

    k_pack<<<2048, 256>>>(adj);
    k_gemm1<<<(B_ * N_) / 64, 256>>>(h, W, a);
    k_maxwh2<<<B_, 256>>>();
    k_attn<<<(B_ * N_ / ITILE) * NSPLIT, 256>>>();
    k_final<<<(B_ * N_ * FOUT) / 1024, 256>>>(out);
}

// round 15
// speedup vs baseline: 3.3155x; 1.2392x over previous
#include <cuda_runtime.h>
#include <cuda_fp16.h>
#include <cstdint>

// Problem constants
#define B_  8
#define N_  2048
#define FIN 256
#define FOUT 64
#define NSPLIT 2
#define JCHUNK (N_ / NSPLIT)   // 1024
#define NCHUNK (JCHUNK / 64)   // 16
#define ITILE  64              // i-rows per block

// Scratch (device globals: allocation-free)
__device__ __half    g_WhT[B_ * FOUT * N_];           // [b][c][j] fp16, 2 MB
__device__ float     g_Wh1[B_ * N_];
__device__ float     g_Wh2[B_ * N_];
__device__ float     g_maxWh2[B_];
__device__ float     g_accp[NSPLIT * B_ * N_ * FOUT]; // partial numerators
__device__ float     g_lpart[NSPLIT * B_ * N_];       // partial denominators

__device__ __forceinline__ uint32_t smem_u32(const void* p) {
    uint32_t a;
    asm("{ .reg .u64 t; cvta.to.shared.u64 t, %1; cvt.u32.u64 %0, t; }" : "=r"(a) : "l"(p));
    return a;
}

// ---------------------------------------------------------------------------
// K0: Wh = h @ W (f32x2 packed FMA); epilogue: Wh1/Wh2 + fp16 WhT transpose.
// Grid: 256 blocks x 256 threads, 64 rows per block.
// ---------------------------------------------------------------------------
__global__ void k_gemm1(const float* __restrict__ h, const float* __restrict__ W,
                        const float* __restrict__ a) {
    __shared__ __align__(16) float hs[64][68];
    __shared__ __align__(16) float Wst[64][68];
    __shared__ float as[128];

    int tid = threadIdx.x;
    int tx = tid & 63, ty = tid >> 6;
    int r0 = blockIdx.x * 64;

    if (tid < 128) as[tid] = a[tid];

    unsigned long long acc64[16];
#pragma unroll
    for (int i = 0; i < 16; i++) acc64[i] = 0ull;

    for (int kt = 0; kt < 4; kt++) {
        __syncthreads();
#pragma unroll
        for (int l = 0; l < 16; l++) {
            int idx = l * 256 + tid;
            int r = idx >> 6, kk = idx & 63;
            hs[r][kk] = h[(size_t)(r0 + r) * FIN + kt * 64 + kk];
        }
#pragma unroll
        for (int l = 0; l < 16; l++) {
            int idx = l * 256 + tid;
            int kk = idx >> 6, c = idx & 63;
            Wst[c][kk] = W[(size_t)(kt * 64 + kk) * FOUT + c];
        }
        __syncthreads();

        for (int kk = 0; kk < 64; kk += 4) {
            ulonglong2 wv = *(const ulonglong2*)&Wst[tx][kk];
#pragma unroll
            for (int i = 0; i < 16; i++) {
                ulonglong2 hv = *(const ulonglong2*)&hs[ty + 4 * i][kk];
                asm("fma.rn.f32x2 %0, %1, %2, %0;" : "+l"(acc64[i]) : "l"(hv.x), "l"(wv.x));
                asm("fma.rn.f32x2 %0, %1, %2, %0;" : "+l"(acc64[i]) : "l"(hv.y), "l"(wv.y));
            }
        }
    }

    float acc[16];
#pragma unroll
    for (int i = 0; i < 16; i++) {
        float lo, hi;
        asm("mov.b64 {%0, %1}, %2;" : "=f"(lo), "=f"(hi) : "l"(acc64[i]));
        acc[i] = lo + hi;
    }

    __syncthreads();
#pragma unroll
    for (int i = 0; i < 16; i++) hs[ty + 4 * i][tx] = acc[i];
    __syncthreads();

    int b  = r0 >> 11;        // batch
    int j0 = r0 & 2047;       // j offset within batch

    // Wh1/Wh2: 4 threads per row
    {
        int row = tid >> 2, q = tid & 3;
        float s1 = 0.f, s2 = 0.f;
#pragma unroll
        for (int i = 0; i < 16; i++) {
            int c = q * 16 + i;
            float v = hs[row][c];
            s1 += v * as[c];
            s2 += v * as[64 + c];
        }
        s1 += __shfl_xor_sync(0xffffffffu, s1, 1);
        s1 += __shfl_xor_sync(0xffffffffu, s1, 2);
        s2 += __shfl_xor_sync(0xffffffffu, s2, 1);
        s2 += __shfl_xor_sync(0xffffffffu, s2, 2);
        if (q == 0) {
            g_Wh1[r0 + row] = s1;
            g_Wh2[r0 + row] = s2;
        }
    }

    // WhT[b][c][j0..j0+63] fp16 (transpose from hs)
    {
        int c = tid >> 2, q = tid & 3;
        __half2 hh[8];
#pragma unroll
        for (int i = 0; i < 8; i++)
            hh[i] = __floats2half2_rn(hs[q * 16 + 2 * i][c], hs[q * 16 + 2 * i + 1][c]);
        uint4 u0 = make_uint4(*(uint32_t*)&hh[0], *(uint32_t*)&hh[1],
                              *(uint32_t*)&hh[2], *(uint32_t*)&hh[3]);
        uint4 u1 = make_uint4(*(uint32_t*)&hh[4], *(uint32_t*)&hh[5],
                              *(uint32_t*)&hh[6], *(uint32_t*)&hh[7]);
        __half* dst = g_WhT + ((size_t)(b * FOUT + c)) * N_ + j0 + q * 16;
        *(uint4*)(dst)     = u0;
        *(uint4*)(dst + 8) = u1;
    }
}

// ---------------------------------------------------------------------------
// K0c: per-batch max of Wh2.
// ---------------------------------------------------------------------------
__global__ void k_maxwh2() {
    __shared__ float red[256];
    int b = blockIdx.x;
    float m = -1e30f;
    for (int i = threadIdx.x; i < N_; i += 256)
        m = fmaxf(m, g_Wh2[(size_t)b * N_ + i]);
    red[threadIdx.x] = m;
    __syncthreads();
    for (int s = 128; s > 0; s >>= 1) {
        if (threadIdx.x < s) red[threadIdx.x] = fmaxf(red[threadIdx.x], red[threadIdx.x + s]);
        __syncthreads();
    }
    if (threadIdx.x == 0) g_maxWh2[b] = red[0];
}

// ---------------------------------------------------------------------------
// K1: attention, HMMA + double-buffered pipeline, RAW adj fused in
// (k_pack deleted: adj's 134 MB now streams through this kernel's idle DRAM,
// overlapped with HMMA via the existing 1-chunk-lookahead producer).
// Grid: 512 blocks (8b x 32 i-tiles(64) x 2 j-splits), 256 threads (8 warps).
// Warp w: rows (w&3)*16..+15, cols (w>>2)*32..+31.
// ---------------------------------------------------------------------------
#define PSTR 72   // padded row stride in halves (144 B): ldmatrix conflict-free

__global__ void __launch_bounds__(256, 4) k_attn(const int* __restrict__ adj) {
    __shared__ __align__(16) __half Ps[2][ITILE][PSTR];   // 18432 B
    __shared__ __align__(16) __half WT[2][64][PSTR];      // 18432 B
    __shared__ float wh1s[ITILE], Mr[ITILE], ls[ITILE];
    __shared__ __align__(16) float wh2s[JCHUNK];          // 4096 B

    int tid  = threadIdx.x;
    int lane = tid & 31;
    int warp = tid >> 5;

    int split = blockIdx.x & (NSPLIT - 1);
    int tile  = blockIdx.x >> 1;
    int b  = tile >> 5;
    int i0 = (tile & 31) * ITILE;
    size_t rowbase = (size_t)b * N_ + i0;
    int jt0 = split * JCHUNK;

    if (tid < ITILE) {
        float w1 = g_Wh1[rowbase + tid];
        wh1s[tid] = w1;
        float s = w1 + g_maxWh2[b];
        Mr[tid] = s > 0.f ? s : 0.2f * s;
    }
    for (int i = tid; i < JCHUNK; i += 256)
        wh2s[i] = g_Wh2[(size_t)b * N_ + jt0 + i];

    // phase-1 mapping: 16 row-slots x 16 j-groups
    int cx = tid & 15, ry = tid >> 4;
    int tjx = cx * 4;
    float lp[4] = {0.f, 0.f, 0.f, 0.f};

    float acc[4][4];
#pragma unroll
    for (int nb = 0; nb < 4; nb++)
#pragma unroll
        for (int q = 0; q < 4; q++) acc[nb][q] = 0.f;

    const int* adjbase = adj + rowbase * N_;

    auto load_adj = [&](int ch, int4* av) {
        int jt = jt0 + ch * 64;
#pragma unroll
        for (int k = 0; k < 4; k++)
            av[k] = *(const int4*)&adjbase[(size_t)(ry + 16 * k) * N_ + jt + tjx];
    };

    auto stage_wt = [&](int ch, int bf) {
        int jt = jt0 + ch * 64;
#pragma unroll
        for (int l = 0; l < 2; l++) {
            int idx = l * 256 + tid;
            int row = idx >> 3, seg = idx & 7;
            uint4 v = *(const uint4*)(g_WhT + ((size_t)(b * FOUT + row)) * N_ + jt + seg * 8);
            *(uint4*)&WT[bf][row][seg * 8] = v;
        }
    };

    auto build_p = [&](int ch, int bf, const int4* av) {
        float4 w2v = *(const float4*)&wh2s[ch * 64 + tjx];
#pragma unroll
        for (int k = 0; k < 4; k++) {
            int row = ry + 16 * k;
            float w1v = wh1s[row], mrv = Mr[row];
            float s, p0, p1, p2, p3;
            s = w1v + w2v.x; s = s > 0.f ? s : 0.2f * s;
            p0 = (av[k].x > 0) ? __expf(s - mrv) : 0.f;
            s = w1v + w2v.y; s = s > 0.f ? s : 0.2f * s;
            p1 = (av[k].y > 0) ? __expf(s - mrv) : 0.f;
            s = w1v + w2v.z; s = s > 0.f ? s : 0.2f * s;
            p2 = (av[k].z > 0) ? __expf(s - mrv) : 0.f;
            s = w1v + w2v.w; s = s > 0.f ? s : 0.2f * s;
            p3 = (av[k].w > 0) ? __expf(s - mrv) : 0.f;
            __half2 h0 = __floats2half2_rn(p0, p1);
            __half2 h1 = __floats2half2_rn(p2, p3);
            // denominator from ROUNDED values (consistent with MMA numerator)
            float2 f0 = __half22float2(h0), f1 = __half22float2(h1);
            lp[k] += (f0.x + f0.y) + (f1.x + f1.y);
            *(uint2*)&Ps[bf][row][tjx] = make_uint2(*(uint32_t*)&h0, *(uint32_t*)&h1);
        }
    };

    // ldmatrix base addresses (buffer 0)
    int iw  = (warp & 3) * 16;   // row base
    int nco = (warp >> 2) * 32;  // col base
    uint32_t a_base = smem_u32(&Ps[0][iw + (lane & 7) + 8 * ((lane >> 3) & 1)]
                                    [8 * ((lane >> 4) & 1)]);
    uint32_t b_base = smem_u32(&WT[0][nco + 8 * ((lane >> 4) & 1) + (lane & 7)]
                                    [8 * ((lane >> 3) & 1)]);
    const uint32_t PSZ = ITILE * PSTR * 2;   // bytes per Ps buffer
    const uint32_t WSZ = 64 * PSTR * 2;      // bytes per WT buffer

    // order wh1s/Mr/wh2s init writes before produce reads them cross-thread
    __syncthreads();

    int4 av[4];
    load_adj(0, av);
    stage_wt(0, 0);
    build_p(0, 0, av);
    __syncthreads();

    for (int ch = 0; ch < NCHUNK; ch++) {
        int cur = ch & 1;
        if (ch + 1 < NCHUNK) {
            load_adj(ch + 1, av);     // DRAM loads issue first...
            stage_wt(ch + 1, cur ^ 1); // ...then L2 loads...
            build_p(ch + 1, cur ^ 1, av); // ...exp consumes after slack
        }

        // consume buffer cur: D += P @ WT^T via mma.sync m16n8k16
        uint32_t aab = a_base + cur * PSZ;
        uint32_t bbb = b_base + cur * WSZ;
#pragma unroll
        for (int k = 0; k < 4; k++) {
            uint32_t a0, a1, a2, a3;
            asm volatile("ldmatrix.sync.aligned.m8n8.x4.shared.b16 {%0,%1,%2,%3}, [%4];"
                         : "=r"(a0), "=r"(a1), "=r"(a2), "=r"(a3)
                         : "r"(aab + k * 32));
#pragma unroll
            for (int nb2 = 0; nb2 < 2; nb2++) {
                uint32_t b0, b1, b2, b3;
                asm volatile("ldmatrix.sync.aligned.m8n8.x4.shared.b16 {%0,%1,%2,%3}, [%4];"
                             : "=r"(b0), "=r"(b1), "=r"(b2), "=r"(b3)
                             : "r"(bbb + nb2 * 16 * (PSTR * 2) + k * 32));
                float* c0 = acc[nb2 * 2];
                float* c1 = acc[nb2 * 2 + 1];
                asm volatile("mma.sync.aligned.m16n8k16.row.col.f32.f16.f16.f32 "
                             "{%0,%1,%2,%3}, {%4,%5,%6,%7}, {%8,%9}, {%0,%1,%2,%3};"
                             : "+f"(c0[0]), "+f"(c0[1]), "+f"(c0[2]), "+f"(c0[3])
                             : "r"(a0), "r"(a1), "r"(a2), "r"(a3), "r"(b0), "r"(b1));
                asm volatile("mma.sync.aligned.m16n8k16.row.col.f32.f16.f16.f32 "
                             "{%0,%1,%2,%3}, {%4,%5,%6,%7}, {%8,%9}, {%0,%1,%2,%3};"
                             : "+f"(c1[0]), "+f"(c1[1]), "+f"(c1[2]), "+f"(c1[3])
                             : "r"(a0), "r"(a1), "r"(a2), "r"(a3), "r"(b2), "r"(b3));
            }
        }
        __syncthreads();
    }

    // ---- denominators (16-lane groups) ----
#pragma unroll
    for (int k = 0; k < 4; k++) {
        float v = lp[k];
        v += __shfl_xor_sync(0xffffffffu, v, 1);
        v += __shfl_xor_sync(0xffffffffu, v, 2);
        v += __shfl_xor_sync(0xffffffffu, v, 4);
        v += __shfl_xor_sync(0xffffffffu, v, 8);
        if ((tid & 15) == 0) ls[ry + 16 * k] = v;
    }
    __syncthreads();

    // ---- store partials ----
    size_t abase = (size_t)split * (B_ * N_) + rowbase;
    if (tid < ITILE) g_lpart[abase + tid] = ls[tid];

    int gid = lane >> 2, tig = lane & 3;
#pragma unroll
    for (int nb = 0; nb < 4; nb++) {
        int col = nco + nb * 8 + tig * 2;
        float2 v0 = {acc[nb][0], acc[nb][1]};
        float2 v1 = {acc[nb][2], acc[nb][3]};
        *(float2*)&g_accp[(abase + iw + gid) * FOUT + col]     = v0;
        *(float2*)&g_accp[(abase + iw + gid + 8) * FOUT + col] = v1;
    }
}

// ---------------------------------------------------------------------------
// K2: combine split partials, normalize, ELU, store.
// ---------------------------------------------------------------------------
__global__ void k_final(float* __restrict__ out) {
    int t = blockIdx.x * 256 + threadIdx.x;
    int row = t >> 4;
    int c4 = (t & 15) * 4;

    float l = 0.f;
    float4 s = {0.f, 0.f, 0.f, 0.f};
#pragma unroll
    for (int sp = 0; sp < NSPLIT; sp++) {
        size_t base = (size_t)sp * (B_ * N_) + row;
        l += g_lpart[base];
        float4 v = *(const float4*)&g_accp[base * FOUT + c4];
        s.x += v.x; s.y += v.y; s.z += v.z; s.w += v.w;
    }
    float inv = 1.f / l;
    float v;
    float4 o;
    v = s.x * inv; o.x = v > 0.f ? v : expm1f(v);
    v = s.y * inv; o.y = v > 0.f ? v : expm1f(v);
    v = s.z * inv; o.z = v > 0.f ? v : expm1f(v);
    v = s.w * inv; o.w = v > 0.f ? v : expm1f(v);
    *(float4*)&out[(size_t)row * FOUT + c4] = o;
}

// ---------------------------------------------------------------------------
extern "C" void kernel_launch(void* const* d_in, const int* in_sizes, int n_in,
                              void* d_out, int out_size) {
    const float* h   = (const float*)d_in[0];
    const int*   adj = (const int*)d_in[1];
    const float* W   = (const float*)d_in[2];
    const float* a   = (const float*)d_in[3];
    float* out = (float*)d_out;

    k_gemm1<<<(B_ * N_) / 64, 256>>>(h, W, a);
    k_maxwh2<<<B_, 256>>>();
    k_attn<<<(B_ * N_ / ITILE) * NSPLIT, 256>>>(adj);
    k_final<<<(B_ * N_ * FOUT) / 1024, 256>>>(out);
}

// round 16
// speedup vs baseline: 3.3886x; 1.0220x over previous
#include <cuda_runtime.h>
#include <cuda_fp16.h>
#include <cstdint>

// Problem constants
#define B_  8
#define N_  2048
#define FIN 256
#define FOUT 64
#define NSPLIT 2
#define JCHUNK (N_ / NSPLIT)   // 1024
#define NCHUNK (JCHUNK / 64)   // 16
#define ITILE  64              // i-rows per attn block

// Scratch (device globals: allocation-free)
__device__ __half    g_WhT[B_ * FOUT * N_];           // [b][c][j] fp16, 2 MB
__device__ float     g_Wh1[B_ * N_];
__device__ float     g_Wh2[B_ * N_];
__device__ float     g_maxWh2[B_];
__device__ float     g_accp[NSPLIT * B_ * N_ * FOUT]; // partial numerators
__device__ float     g_lpart[NSPLIT * B_ * N_];       // partial denominators

__device__ __forceinline__ uint32_t smem_u32(const void* p) {
    uint32_t a;
    asm("{ .reg .u64 t; cvta.to.shared.u64 t, %1; cvt.u32.u64 %0, t; }" : "=r"(a) : "l"(p));
    return a;
}

// ---------------------------------------------------------------------------
// K0: Wh = h @ W (f32x2 FMA); epilogue: Wh1/Wh2 + fp16 WhT transpose.
// Grid: 512 blocks x 256 threads, 32 rows per block (3.5 blocks/SM vs 1.7).
// ---------------------------------------------------------------------------
__global__ void k_gemm1(const float* __restrict__ h, const float* __restrict__ W,
                        const float* __restrict__ a) {
    __shared__ __align__(16) float hs[32][68];
    __shared__ __align__(16) float Wst[64][68];
    __shared__ float as[128];

    int tid = threadIdx.x;
    int tx = tid & 63, ty = tid >> 6;
    int r0 = blockIdx.x * 32;

    if (tid < 128) as[tid] = a[tid];

    unsigned long long acc64[8];
#pragma unroll
    for (int i = 0; i < 8; i++) acc64[i] = 0ull;

    for (int kt = 0; kt < 4; kt++) {
        __syncthreads();
#pragma unroll
        for (int l = 0; l < 8; l++) {
            int idx = l * 256 + tid;
            int r = idx >> 6, kk = idx & 63;
            hs[r][kk] = h[(size_t)(r0 + r) * FIN + kt * 64 + kk];
        }
#pragma unroll
        for (int l = 0; l < 16; l++) {
            int idx = l * 256 + tid;
            int kk = idx >> 6, c = idx & 63;
            Wst[c][kk] = W[(size_t)(kt * 64 + kk) * FOUT + c];
        }
        __syncthreads();

        for (int kk = 0; kk < 64; kk += 4) {
            ulonglong2 wv = *(const ulonglong2*)&Wst[tx][kk];
#pragma unroll
            for (int i = 0; i < 8; i++) {
                ulonglong2 hv = *(const ulonglong2*)&hs[ty + 4 * i][kk];
                asm("fma.rn.f32x2 %0, %1, %2, %0;" : "+l"(acc64[i]) : "l"(hv.x), "l"(wv.x));
                asm("fma.rn.f32x2 %0, %1, %2, %0;" : "+l"(acc64[i]) : "l"(hv.y), "l"(wv.y));
            }
        }
    }

    float acc[8];
#pragma unroll
    for (int i = 0; i < 8; i++) {
        float lo, hi;
        asm("mov.b64 {%0, %1}, %2;" : "=f"(lo), "=f"(hi) : "l"(acc64[i]));
        acc[i] = lo + hi;
    }

    __syncthreads();
#pragma unroll
    for (int i = 0; i < 8; i++) hs[ty + 4 * i][tx] = acc[i];
    __syncthreads();

    int b  = r0 >> 11;        // batch
    int j0 = r0 & 2047;       // j offset within batch

    // Wh1/Wh2: 8 threads per row (32 rows x 8 = 256)
    {
        int row = tid >> 3, q = tid & 7;
        float s1 = 0.f, s2 = 0.f;
#pragma unroll
        for (int i = 0; i < 8; i++) {
            int c = q * 8 + i;
            float v = hs[row][c];
            s1 += v * as[c];
            s2 += v * as[64 + c];
        }
        s1 += __shfl_xor_sync(0xffffffffu, s1, 1);
        s1 += __shfl_xor_sync(0xffffffffu, s1, 2);
        s1 += __shfl_xor_sync(0xffffffffu, s1, 4);
        s2 += __shfl_xor_sync(0xffffffffu, s2, 1);
        s2 += __shfl_xor_sync(0xffffffffu, s2, 2);
        s2 += __shfl_xor_sync(0xffffffffu, s2, 4);
        if (q == 0) {
            g_Wh1[r0 + row] = s1;
            g_Wh2[r0 + row] = s2;
        }
    }

    // WhT[b][c][j0..j0+31] fp16 (transpose from hs): 64 cols x 4 j-quarters of 8
    {
        int c = tid >> 2, q = tid & 3;
        __half2 hh[4];
#pragma unroll
        for (int i = 0; i < 4; i++)
            hh[i] = __floats2half2_rn(hs[q * 8 + 2 * i][c], hs[q * 8 + 2 * i + 1][c]);
        uint4 u0 = make_uint4(*(uint32_t*)&hh[0], *(uint32_t*)&hh[1],
                              *(uint32_t*)&hh[2], *(uint32_t*)&hh[3]);
        *(uint4*)(g_WhT + ((size_t)(b * FOUT + c)) * N_ + j0 + q * 8) = u0;
    }
}

// ---------------------------------------------------------------------------
// K0c: per-batch max of Wh2.
// ---------------------------------------------------------------------------
__global__ void k_maxwh2() {
    __shared__ float red[256];
    int b = blockIdx.x;
    float m = -1e30f;
    for (int i = threadIdx.x; i < N_; i += 256)
        m = fmaxf(m, g_Wh2[(size_t)b * N_ + i]);
    red[threadIdx.x] = m;
    __syncthreads();
    for (int s = 128; s > 0; s >>= 1) {
        if (threadIdx.x < s) red[threadIdx.x] = fmaxf(red[threadIdx.x], red[threadIdx.x + s]);
        __syncthreads();
    }
    if (threadIdx.x == 0) g_maxWh2[b] = red[0];
}

// ---------------------------------------------------------------------------
// K1: attention, HMMA + double-buffered pipeline, raw adj fused.
// R16 reorder: adj loads for ch+1 issue BEFORE consume(ch); exp/staging run
// AFTER it -> each warp's own MMA section hides its adj DRAM latency.
// Grid: 512 blocks (8b x 32 i-tiles(64) x 2 j-splits), 256 threads (8 warps).
// ---------------------------------------------------------------------------
#define PSTR 72   // padded row stride in halves (144 B): ldmatrix conflict-free

__global__ void __launch_bounds__(256, 4) k_attn(const int* __restrict__ adj) {
    __shared__ __align__(16) __half Ps[2][ITILE][PSTR];   // 18432 B
    __shared__ __align__(16) __half WT[2][64][PSTR];      // 18432 B
    __shared__ float wh1s[ITILE], Mr[ITILE], ls[ITILE];
    __shared__ __align__(16) float wh2s[JCHUNK];          // 4096 B

    int tid  = threadIdx.x;
    int lane = tid & 31;
    int warp = tid >> 5;

    int split = blockIdx.x & (NSPLIT - 1);
    int tile  = blockIdx.x >> 1;
    int b  = tile >> 5;
    int i0 = (tile & 31) * ITILE;
    size_t rowbase = (size_t)b * N_ + i0;
    int jt0 = split * JCHUNK;

    if (tid < ITILE) {
        float w1 = g_Wh1[rowbase + tid];
        wh1s[tid] = w1;
        float s = w1 + g_maxWh2[b];
        Mr[tid] = s > 0.f ? s : 0.2f * s;
    }
    for (int i = tid; i < JCHUNK; i += 256)
        wh2s[i] = g_Wh2[(size_t)b * N_ + jt0 + i];

    int cx = tid & 15, ry = tid >> 4;
    int tjx = cx * 4;
    float lp[4] = {0.f, 0.f, 0.f, 0.f};

    float acc[4][4];
#pragma unroll
    for (int nb = 0; nb < 4; nb++)
#pragma unroll
        for (int q = 0; q < 4; q++) acc[nb][q] = 0.f;

    const int* adjbase = adj + rowbase * N_;

    auto load_adj = [&](int ch, int4* av) {
        int jt = jt0 + ch * 64;
#pragma unroll
        for (int k = 0; k < 4; k++)
            av[k] = *(const int4*)&adjbase[(size_t)(ry + 16 * k) * N_ + jt + tjx];
    };

    auto stage_wt = [&](int ch, int bf) {
        int jt = jt0 + ch * 64;
#pragma unroll
        for (int l = 0; l < 2; l++) {
            int idx = l * 256 + tid;
            int row = idx >> 3, seg = idx & 7;
            uint4 v = *(const uint4*)(g_WhT + ((size_t)(b * FOUT + row)) * N_ + jt + seg * 8);
            *(uint4*)&WT[bf][row][seg * 8] = v;
        }
    };

    auto build_p = [&](int ch, int bf, const int4* av) {
        float4 w2v = *(const float4*)&wh2s[ch * 64 + tjx];
#pragma unroll
        for (int k = 0; k < 4; k++) {
            int row = ry + 16 * k;
            float w1v = wh1s[row], mrv = Mr[row];
            float s, p0, p1, p2, p3;
            s = w1v + w2v.x; s = s > 0.f ? s : 0.2f * s;
            p0 = (av[k].x > 0) ? __expf(s - mrv) : 0.f;
            s = w1v + w2v.y; s = s > 0.f ? s : 0.2f * s;
            p1 = (av[k].y > 0) ? __expf(s - mrv) : 0.f;
            s = w1v + w2v.z; s = s > 0.f ? s : 0.2f * s;
            p2 = (av[k].z > 0) ? __expf(s - mrv) : 0.f;
            s = w1v + w2v.w; s = s > 0.f ? s : 0.2f * s;
            p3 = (av[k].w > 0) ? __expf(s - mrv) : 0.f;
            __half2 h0 = __floats2half2_rn(p0, p1);
            __half2 h1 = __floats2half2_rn(p2, p3);
            // denominator from ROUNDED values (consistent with MMA numerator)
            float2 f0 = __half22float2(h0), f1 = __half22float2(h1);
            lp[k] += (f0.x + f0.y) + (f1.x + f1.y);
            *(uint2*)&Ps[bf][row][tjx] = make_uint2(*(uint32_t*)&h0, *(uint32_t*)&h1);
        }
    };

    // ldmatrix base addresses (buffer 0)
    int iw  = (warp & 3) * 16;   // row base
    int nco = (warp >> 2) * 32;  // col base
    uint32_t a_base = smem_u32(&Ps[0][iw + (lane & 7) + 8 * ((lane >> 3) & 1)]
                                    [8 * ((lane >> 4) & 1)]);
    uint32_t b_base = smem_u32(&WT[0][nco + 8 * ((lane >> 4) & 1) + (lane & 7)]
                                    [8 * ((lane >> 3) & 1)]);
    const uint32_t PSZ = ITILE * PSTR * 2;
    const uint32_t WSZ = 64 * PSTR * 2;

    // order wh1s/Mr/wh2s init writes before first cross-thread reads
    __syncthreads();

    int4 av[4];
    load_adj(0, av);
    stage_wt(0, 0);
    build_p(0, 0, av);
    __syncthreads();

    for (int ch = 0; ch < NCHUNK; ch++) {
        int cur = ch & 1;
        bool more = (ch + 1 < NCHUNK);

        if (more) load_adj(ch + 1, av);   // adj DRAM loads issue NOW...

        // ...and the MMA consume section hides their latency
        uint32_t aab = a_base + cur * PSZ;
        uint32_t bbb = b_base + cur * WSZ;
#pragma unroll
        for (int k = 0; k < 4; k++) {
            uint32_t a0, a1, a2, a3;
            asm volatile("ldmatrix.sync.aligned.m8n8.x4.shared.b16 {%0,%1,%2,%3}, [%4];"
                         : "=r"(a0), "=r"(a1), "=r"(a2), "=r"(a3)
                         : "r"(aab + k * 32));
#pragma unroll
            for (int nb2 = 0; nb2 < 2; nb2++) {
                uint32_t b0, b1, b2, b3;
                asm volatile("ldmatrix.sync.aligned.m8n8.x4.shared.b16 {%0,%1,%2,%3}, [%4];"
                             : "=r"(b0), "=r"(b1), "=r"(b2), "=r"(b3)
                             : "r"(bbb + nb2 * 16 * (PSTR * 2) + k * 32));
                float* c0 = acc[nb2 * 2];
                float* c1 = acc[nb2 * 2 + 1];
                asm volatile("mma.sync.aligned.m16n8k16.row.col.f32.f16.f16.f32 "
                             "{%0,%1,%2,%3}, {%4,%5,%6,%7}, {%8,%9}, {%0,%1,%2,%3};"
                             : "+f"(c0[0]), "+f"(c0[1]), "+f"(c0[2]), "+f"(c0[3])
                             : "r"(a0), "r"(a1), "r"(a2), "r"(a3), "r"(b0), "r"(b1));
                asm volatile("mma.sync.aligned.m16n8k16.row.col.f32.f16.f16.f32 "
                             "{%0,%1,%2,%3}, {%4,%5,%6,%7}, {%8,%9}, {%0,%1,%2,%3};"
                             : "+f"(c1[0]), "+f"(c1[1]), "+f"(c1[2]), "+f"(c1[3])
                             : "r"(a0), "r"(a1), "r"(a2), "r"(a3), "r"(b2), "r"(b3));
            }
        }

        if (more) {
            stage_wt(ch + 1, cur ^ 1);
            build_p(ch + 1, cur ^ 1, av);
        }
        __syncthreads();
    }

    // ---- denominators (16-lane groups) ----
#pragma unroll
    for (int k = 0; k < 4; k++) {
        float v = lp[k];
        v += __shfl_xor_sync(0xffffffffu, v, 1);
        v += __shfl_xor_sync(0xffffffffu, v, 2);
        v += __shfl_xor_sync(0xffffffffu, v, 4);
        v += __shfl_xor_sync(0xffffffffu, v, 8);
        if ((tid & 15) == 0) ls[ry + 16 * k] = v;
    }
    __syncthreads();

    // ---- store partials ----
    size_t abase = (size_t)split * (B_ * N_) + rowbase;
    if (tid < ITILE) g_lpart[abase + tid] = ls[tid];

    int gid = lane >> 2, tig = lane & 3;
#pragma unroll
    for (int nb = 0; nb < 4; nb++) {
        int col = nco + nb * 8 + tig * 2;
        float2 v0 = {acc[nb][0], acc[nb][1]};
        float2 v1 = {acc[nb][2], acc[nb][3]};
        *(float2*)&g_accp[(abase + iw + gid) * FOUT + col]     = v0;
        *(float2*)&g_accp[(abase + iw + gid + 8) * FOUT + col] = v1;
    }
}

// ---------------------------------------------------------------------------
// K2: combine split partials, normalize, ELU, store.
// ---------------------------------------------------------------------------
__global__ void k_final(float* __restrict__ out) {
    int t = blockIdx.x * 256 + threadIdx.x;
    int row = t >> 4;
    int c4 = (t & 15) * 4;

    float l = 0.f;
    float4 s = {0.f, 0.f, 0.f, 0.f};
#pragma unroll
    for (int sp = 0; sp < NSPLIT; sp++) {
        size_t base = (size_t)sp * (B_ * N_) + row;
        l += g_lpart[base];
        float4 v = *(const float4*)&g_accp[base * FOUT + c4];
        s.x += v.x; s.y += v.y; s.z += v.z; s.w += v.w;
    }
    float inv = 1.f / l;
    float v;
    float4 o;
    v = s.x * inv; o.x = v > 0.f ? v : expm1f(v);
    v = s.y * inv; o.y = v > 0.f ? v : expm1f(v);
    v = s.z * inv; o.z = v > 0.f ? v : expm1f(v);
    v = s.w * inv; o.w = v > 0.f ? v : expm1f(v);
    *(float4*)&out[(size_t)row * FOUT + c4] = o;
}

// ---------------------------------------------------------------------------
extern "C" void kernel_launch(void* const* d_in, const int* in_sizes, int n_in,
                              void* d_out, int out_size) {
    const float* h   = (const float*)d_in[0];
    const int*   adj = (const int*)d_in[1];
    const float* W   = (const float*)d_in[2];
    const float* a   = (const float*)d_in[3];
    float* out = (float*)d_out;

    k_gemm1<<<(B_ * N_) / 32, 256>>>(h, W, a);
    k_maxwh2<<<B_, 256>>>();
    k_attn<<<(B_ * N_ / ITILE) * NSPLIT, 256>>>(adj);
    k_final<<<(B_ * N_ * FOUT) / 1024, 256>>>(out);
}